// round 14
// baseline (speedup 1.0000x reference)
#include <cuda_runtime.h>
#include <cuda_bf16.h>
#include <math.h>
#include <stdint.h>

// ---------------- problem constants ----------------
constexpr int NB = 4096;   // batch
constexpr int ND = 1024;   // model dim
constexpr int NT = 768;    // text dim
constexpr int NC = 16;     // classes
constexpr int NH = 4;      // heads
constexpr int NS = 4;      // sequence length of stacked features
constexpr int HD = ND / NH; // 256

#define CURV 0.05f
#define SQC  0.22360679774997896f       // sqrt(0.05)
#define EPSF 1e-8f
#define ASINH_MAX 11.090354888959125f   // arcsinh(2^15)

// output layout (flattened tuple: logits, loss, oh, fh, oeu, feu)
constexpr long long LOSS_OFF = (long long)NB * NC;
constexpr long long OH_OFF   = LOSS_OFF + 1;
constexpr long long FH_OFF   = OH_OFF  + (long long)NB * ND;
constexpr long long OEU_OFF  = FH_OFF  + (long long)NB * ND;
constexpr long long FEU_OFF  = OEU_OFF + (long long)NB * ND;

// ---------------- device scratch ----------------
__device__ float g_gf0 [(size_t)NB * NS * ND];
__device__ float g_qkv [(size_t)NB * NS * 3 * ND];
__device__ float g_ctx [(size_t)NB * NS * ND];
__device__ float g_attn[(size_t)NB * NS * ND];
__device__ float g_uo  [(size_t)NB * ND];
__device__ float g_uf  [(size_t)NB * ND];
__device__ float g_pen [2 * NB];
__device__ float g_pp  [NC * ND];
__device__ float g_ap  [NC * ND];
__device__ float g_cs  [4 * NC];

// split-bf16 staging: activations (reused: gf0_3 -> ctx3 -> order3+family3)
__device__ __nv_bfloat16 g_a3[(size_t)NB * NS * 3 * ND];
// weights, split-bf16
constexpr size_t W_IN3_OFF  = 0;                                      // 3072 x 3072
constexpr size_t W_OUT3_OFF = W_IN3_OFF  + (size_t)3 * ND * 3 * ND;   // 1024 x 3072
constexpr size_t W_TO3_OFF  = W_OUT3_OFF + (size_t)ND * 3 * ND;       // 1024 x 2304
constexpr size_t W_TF3_OFF  = W_TO3_OFF  + (size_t)ND * 3 * NT;
__device__ __nv_bfloat16 g_w3[W_TF3_OFF + (size_t)ND * 3 * NT];
constexpr size_t FAM3_OFF = (size_t)NB * 3 * NT;

// ---------------- small helpers ----------------
__device__ __forceinline__ float blockReduceSum(float v, volatile float* sh) {
    int lane = threadIdx.x & 31, wid = threadIdx.x >> 5;
#pragma unroll
    for (int o = 16; o > 0; o >>= 1) v += __shfl_down_sync(0xffffffffu, v, o);
    if (lane == 0) sh[wid] = v;
    __syncthreads();
    if (wid == 0) {
        int nw = (blockDim.x + 31) >> 5;
        float t = (lane < nw) ? sh[lane] : 0.f;
#pragma unroll
        for (int o = 16; o > 0; o >>= 1) t += __shfl_down_sync(0xffffffffu, t, o);
        if (lane == 0) sh[32] = t;
    }
    __syncthreads();
    float r = sh[32];
    __syncthreads();
    return r;
}

__device__ __forceinline__ uint32_t smem_u32(const void* p) {
    uint32_t a;
    asm("{ .reg .u64 t; cvta.to.shared.u64 t, %1; cvt.u32.u64 %0, t; }" : "=r"(a) : "l"(p));
    return a;
}

#define SWZ(o) ((o) ^ (((o) >> 3) & 0x70))

__device__ __forceinline__ void cp16(uint32_t dst, const void* src) {
    asm volatile("cp.async.cg.shared.global [%0], [%1], 16;" :: "r"(dst), "l"(src));
}
__device__ __forceinline__ void cp_commit() {
    asm volatile("cp.async.commit_group;" ::: "memory");
}
__device__ __forceinline__ void cp_wait1() {
    asm volatile("cp.async.wait_group 1;" ::: "memory");
}
__device__ __forceinline__ void ldm4(uint32_t* r, uint32_t a) {
    asm volatile("ldmatrix.sync.aligned.m8n8.x4.shared.b16 {%0,%1,%2,%3}, [%4];"
                 : "=r"(r[0]), "=r"(r[1]), "=r"(r[2]), "=r"(r[3]) : "r"(a));
}
__device__ __forceinline__ void mma16816(float* d, const uint32_t* a, uint32_t b0, uint32_t b1) {
    asm volatile(
        "mma.sync.aligned.m16n8k16.row.col.f32.bf16.bf16.f32 "
        "{%0,%1,%2,%3},{%4,%5,%6,%7},{%8,%9},{%0,%1,%2,%3};"
        : "+f"(d[0]), "+f"(d[1]), "+f"(d[2]), "+f"(d[3])
        : "r"(a[0]), "r"(a[1]), "r"(a[2]), "r"(a[3]), "r"(b0), "r"(b1));
}

// ---------------- mma.sync GEMM: C[M,N] = A[M,K3] @ B[N,K3]^T + bias ----------------
// 128x128 tile, BK=64 bf16 (128B rows, SW128 swizzle), 3-stage cp.async pipeline
constexpr uint32_t AB_STAGE  = 128 * 128;      // 16 KB per operand per stage
constexpr uint32_t STAGE_B   = 2 * AB_STAGE;   // 32 KB
constexpr int      STAGES    = 3;
constexpr uint32_t SMEM_GEMM = STAGES * STAGE_B;   // 96 KB

__device__ __forceinline__ void load_stage(uint32_t sb, int s,
                                           const __nv_bfloat16* Ab, const __nv_bfloat16* Bb,
                                           int K3, int kt, int tid) {
    uint32_t aS = sb + (uint32_t)s * STAGE_B;
    uint32_t bS = aS + AB_STAGE;
    const __nv_bfloat16* Ap = Ab + (size_t)kt * 64;
    const __nv_bfloat16* Bp = Bb + (size_t)kt * 64;
#pragma unroll
    for (int u = 0; u < 4; u++) {
        int id = tid + u * 256;
        int row = id >> 3, ch = id & 7;
        uint32_t o = SWZ((uint32_t)row * 128 + ch * 16);
        cp16(aS + o, Ap + (size_t)row * K3 + ch * 8);
        cp16(bS + o, Bp + (size_t)row * K3 + ch * 8);
    }
    cp_commit();
}

__global__ __launch_bounds__(256)
void k_gemm_mma(const __nv_bfloat16* __restrict__ A, const __nv_bfloat16* __restrict__ B,
                const float* __restrict__ bias, float* __restrict__ C,
                int M, int N, int K3) {
    extern __shared__ char smem[];
    uint32_t sb = smem_u32(smem);
    int tid = threadIdx.x, wid = tid >> 5, lane = tid & 31;
    int wm = wid >> 1, wn = wid & 1;           // 4x2 warp grid
    int lr = lane & 7, mi = lane >> 3;

    int bm = blockIdx.y * 128;
    int bn = blockIdx.x * 128;
    const __nv_bfloat16* Ab = A + (size_t)bm * K3;
    const __nv_bfloat16* Bb = B + (size_t)bn * K3;
    const int NK = K3 >> 6;

    // per-lane ldmatrix address precompute
    int aR = wm * 32 + lr + (mi & 1) * 8;      // + i*16 per m-atom
    uint32_t aKh = (uint32_t)(mi >> 1) * 16;
    uint32_t xa = (uint32_t)(aR & 7) * 16;
    uint32_t aOff0 = (uint32_t)aR * 128;
    uint32_t aOff1 = aOff0 + 16 * 128;
    int bR = wn * 64 + lr + (mi >> 1) * 8;     // + j2*16 per n-atom-pair
    uint32_t bKh = (uint32_t)(mi & 1) * 16;
    uint32_t xb = (uint32_t)(bR & 7) * 16;
    uint32_t bOff[4];
#pragma unroll
    for (int j2 = 0; j2 < 4; j2++) bOff[j2] = (uint32_t)(bR + j2 * 16) * 128;

    float acc[2][8][4];
#pragma unroll
    for (int i = 0; i < 2; i++)
#pragma unroll
        for (int j = 0; j < 8; j++)
#pragma unroll
            for (int r = 0; r < 4; r++) acc[i][j][r] = 0.f;

    load_stage(sb, 0, Ab, Bb, K3, 0, tid);
    load_stage(sb, 1, Ab, Bb, K3, 1, tid);

    for (int kt = 0; kt < NK; kt++) {
        cp_wait1();
        __syncthreads();
        int s = kt % STAGES;
        uint32_t aS = sb + (uint32_t)s * STAGE_B;
        uint32_t bS = aS + AB_STAGE;
#pragma unroll
        for (int ks = 0; ks < 4; ks++) {
            uint32_t kb = (uint32_t)ks * 32;
            uint32_t afrag[2][4];
            ldm4(afrag[0], aS + aOff0 + ((kb + aKh) ^ xa));
            ldm4(afrag[1], aS + aOff1 + ((kb + aKh) ^ xa));
            uint32_t bfrag[4][4];
#pragma unroll
            for (int j2 = 0; j2 < 4; j2++)
                ldm4(bfrag[j2], bS + bOff[j2] + ((kb + bKh) ^ xb));
#pragma unroll
            for (int i = 0; i < 2; i++)
#pragma unroll
                for (int j = 0; j < 8; j++)
                    mma16816(acc[i][j], afrag[i],
                             bfrag[j >> 1][(j & 1) * 2], bfrag[j >> 1][(j & 1) * 2 + 1]);
        }
        if (kt + 2 < NK) load_stage(sb, (kt + 2) % STAGES, Ab, Bb, K3, kt + 2, tid);
        else cp_commit();
    }

    // epilogue: direct float2 stores with bias
    int mBase = bm + wm * 32 + (lane >> 2);
    int nBase = bn + wn * 64 + 2 * (lane & 3);
#pragma unroll
    for (int i = 0; i < 2; i++) {
        int m0 = mBase + i * 16;
#pragma unroll
        for (int j = 0; j < 8; j++) {
            int n = nBase + j * 8;
            float bx = bias[n], by = bias[n + 1];
            float2 v0 = { acc[i][j][0] + bx, acc[i][j][1] + by };
            float2 v1 = { acc[i][j][2] + bx, acc[i][j][3] + by };
            *(float2*)(C + (size_t)m0 * N + n) = v0;
            *(float2*)(C + (size_t)(m0 + 8) * N + n) = v1;
        }
    }
}

// ---------------- split-bf16 converter ----------------
// weightMode=0 (activation): [hi | hi | lo];  weightMode=1 (weight): [hi | lo | hi]
__global__ void k_cvt3(const float* __restrict__ src, __nv_bfloat16* __restrict__ dst,
                       int K, int weightMode) {
    int r = blockIdx.y;
    int k = blockIdx.x * 256 + threadIdx.x;
    float x = src[(size_t)r * K + k];
    __nv_bfloat16 hi = __float2bfloat16(x);
    __nv_bfloat16 lo = __float2bfloat16(x - __bfloat162float(hi));
    size_t b3 = (size_t)r * 3 * K;
    dst[b3 + k] = hi;
    dst[b3 + K + k]     = weightMode ? lo : hi;
    dst[b3 + 2 * K + k] = weightMode ? hi : lo;
}

// ---------------- 1) gf0 = stack(p_logmap0(oh), p_logmap0(fh), oeu, feu) + split ----------------
__global__ void k_prep_gf(const float* __restrict__ ohy, const float* __restrict__ fhy,
                          const float* __restrict__ oeu, const float* __restrict__ feu) {
    int b = blockIdx.x, s = blockIdx.y;
    const float* src = (s == 0) ? ohy : (s == 1) ? fhy : (s == 2) ? oeu : feu;
    src += (size_t)b * ND;
    size_t row = (size_t)b * NS + s;
    float* dst = g_gf0 + row * ND;
    __nv_bfloat16* d3 = g_a3 + row * 3 * ND;
    __shared__ float sh[33];
    float f = 1.f;
    if (s < 2) {
        float acc = 0.f;
        for (int i = threadIdx.x; i < ND; i += blockDim.x) { float v = src[i]; acc += v * v; }
        float n2 = blockReduceSum(acc, sh);
        float n = fmaxf(sqrtf(n2), 1e-15f);
        float t = fminf(SQC * n, 1.f - 1e-5f);
        float art = 0.5f * (log1pf(t) - log1pf(-t));
        f = art / (n * SQC);
    }
    for (int i = threadIdx.x; i < ND; i += blockDim.x) {
        float v = src[i] * f;
        dst[i] = v;
        __nv_bfloat16 hi = __float2bfloat16(v);
        __nv_bfloat16 lo = __float2bfloat16(v - __bfloat162float(hi));
        d3[i] = hi; d3[ND + i] = hi; d3[2 * ND + i] = lo;
    }
}

// ---------------- 2) attention ----------------
__global__ void k_attn() {
    int bh = blockIdx.x;
    int b = bh >> 2, h = bh & 3;
    __shared__ float q[NS][HD], kk[NS][HD], v[NS][HD];
    __shared__ float sc[NS][NS];
    int tid = threadIdx.x;
    const float* base = g_qkv + (size_t)b * NS * 3 * ND;
#pragma unroll
    for (int si = 0; si < NS; si++) {
        q [si][tid] = base[si * 3 * ND +          h * HD + tid];
        kk[si][tid] = base[si * 3 * ND + ND     + h * HD + tid];
        v [si][tid] = base[si * 3 * ND + 2 * ND + h * HD + tid];
    }
    __syncthreads();
    int w = tid >> 5, lane = tid & 31;
    for (int p = w; p < 16; p += 8) {
        int i = p >> 2, j = p & 3;
        float s = 0.f;
        for (int d = lane; d < HD; d += 32) s += q[i][d] * kk[j][d];
#pragma unroll
        for (int o = 16; o > 0; o >>= 1) s += __shfl_down_sync(0xffffffffu, s, o);
        if (lane == 0) sc[i][j] = s * 0.0625f;
    }
    __syncthreads();
    if (tid < 4) {
        float s0 = sc[tid][0], s1 = sc[tid][1], s2 = sc[tid][2], s3 = sc[tid][3];
        float m = fmaxf(fmaxf(s0, s1), fmaxf(s2, s3));
        float e0 = expf(s0 - m), e1 = expf(s1 - m), e2 = expf(s2 - m), e3 = expf(s3 - m);
        float inv = 1.f / (e0 + e1 + e2 + e3);
        sc[tid][0] = e0 * inv; sc[tid][1] = e1 * inv; sc[tid][2] = e2 * inv; sc[tid][3] = e3 * inv;
    }
    __syncthreads();
#pragma unroll
    for (int i = 0; i < NS; i++) {
        float o = sc[i][0] * v[0][tid] + sc[i][1] * v[1][tid] + sc[i][2] * v[2][tid] + sc[i][3] * v[3][tid];
        g_ctx[((size_t)b * NS + i) * ND + h * HD + tid] = o;
    }
}

// ---------------- 3) layernorm + l_expmap0 ----------------
__global__ void k_ln_map(const float* __restrict__ ln_w, const float* __restrict__ ln_b,
                         float* __restrict__ dout) {
    int b = blockIdx.x, s = blockIdx.y;
    size_t off = ((size_t)b * NS + s) * ND;
    __shared__ float sh[33];
    int tid = threadIdx.x;
    float x[4];
    float sum = 0.f;
#pragma unroll
    for (int r = 0; r < 4; r++) {
        int i = tid + r * 256;
        x[r] = g_gf0[off + i] + g_attn[off + i];
        sum += x[r];
    }
    float mu = blockReduceSum(sum, sh) * (1.f / ND);
    float vs = 0.f;
#pragma unroll
    for (int r = 0; r < 4; r++) { float d = x[r] - mu; vs += d * d; }
    float var = blockReduceSum(vs, sh) * (1.f / ND);
    float rstd = rsqrtf(var + 1e-5f);
    float y[4];
#pragma unroll
    for (int r = 0; r < 4; r++) {
        int i = tid + r * 256;
        y[r] = (x[r] - mu) * rstd * ln_w[i] + ln_b[i];
    }
    long long base = (s == 0) ? OH_OFF : (s == 1) ? FH_OFF : (s == 2) ? OEU_OFF : FEU_OFF;
    float* dst = dout + base + (size_t)b * ND;
    if (s < 2) {
        float n2acc = 0.f;
#pragma unroll
        for (int r = 0; r < 4; r++) n2acc += y[r] * y[r];
        float n2 = blockReduceSum(n2acc, sh);
        float rc = SQC * sqrtf(n2);
        float si = fminf(fmaxf(rc, EPSF), ASINH_MAX);
        float f = sinhf(si) / fmaxf(rc, EPSF);
#pragma unroll
        for (int r = 0; r < 4; r++) dst[tid + r * 256] = y[r] * f;
    } else {
#pragma unroll
        for (int r = 0; r < 4; r++) dst[tid + r * 256] = y[r];
    }
}

// ---------------- 4) entailment penalties ----------------
__global__ void k_pen(const float* __restrict__ dout) {
    int b = blockIdx.x, which = blockIdx.y;
    const float* u = (which ? g_uf : g_uo) + (size_t)b * ND;
    const float* y = dout + (which ? OH_OFF : FH_OFF) + (size_t)b * ND;
    __shared__ float sh[33];
    int tid = threadIdx.x;
    float su2 = 0.f, suy = 0.f, sy2 = 0.f;
#pragma unroll
    for (int r = 0; r < 4; r++) {
        int i = tid + r * 256;
        float uu = u[i], yy = y[i];
        su2 += uu * uu; suy += uu * yy; sy2 += yy * yy;
    }
    su2 = blockReduceSum(su2, sh);
    suy = blockReduceSum(suy, sh);
    sy2 = blockReduceSum(sy2, sh);
    if (tid == 0) {
        float ru = sqrtf(su2);
        float rc = SQC * ru;
        float si = fminf(fmaxf(rc, EPSF), ASINH_MAX);
        float f = sinhf(si) / fmaxf(rc, EPSF);
        float xx = f * f * su2;
        float xy = f * suy;
        float yy = sy2;
        float nx = f * ru;
        float xt = sqrtf(1.f / CURV + xx);
        float yt = sqrtf(1.f / CURV + yy);
        float cxy = CURV * (xy - xt * yt);
        float num = yt + cxy * xt;
        float den = sqrtf(fmaxf(cxy * cxy - 1.f, EPSF));
        float acos_in = num / (nx * den + EPSF);
        acos_in = fminf(fmaxf(acos_in, -1.f + EPSF), 1.f - EPSF);
        float angle = acosf(acos_in);
        float asin_in = 0.2f / (nx * SQC + EPSF);
        asin_in = fminf(fmaxf(asin_in, -1.f + EPSF), 1.f - EPSF);
        float ap = asinf(asin_in);
        g_pen[which * NB + b] = fmaxf(angle - ap, 0.f);
    }
}

// ---------------- 5) loss reduction ----------------
__global__ void k_loss(const int* __restrict__ mask, float* __restrict__ dout) {
    __shared__ float sh[33];
    int tid = threadIdx.x;
    float so = 0.f, sf = 0.f, cnt = 0.f;
    for (int i = tid; i < NB; i += blockDim.x) {
        so += g_pen[i];
        float m = (float)mask[i];
        sf += g_pen[NB + i] * m;
        cnt += m;
    }
    so = blockReduceSum(so, sh);
    sf = blockReduceSum(sf, sh);
    cnt = blockReduceSum(cnt, sh);
    if (tid == 0) {
        float ol = so * (1.f / NB);
        float fl = (cnt > 0.f) ? sf / fmaxf(cnt, 1.f) : 0.f;
        dout[LOSS_OFF] = ol + fl;
    }
}

// ---------------- 6) per-class MLR constants ----------------
__global__ void k_cls(const float* __restrict__ a, const float* __restrict__ p) {
    int c = blockIdx.x;
    const float* pr = p + (size_t)c * ND;
    const float* ar = a + (size_t)c * ND;
    __shared__ float sh[33];
    int tid = threadIdx.x;
    float sp2 = 0.f, sa2 = 0.f, spa = 0.f;
#pragma unroll
    for (int r = 0; r < 4; r++) {
        int i = tid + r * 256;
        float pv = pr[i], av = ar[i];
        sp2 += pv * pv; sa2 += av * av; spa += pv * av;
    }
    sp2 = blockReduceSum(sp2, sh);
    sa2 = blockReduceSum(sa2, sh);
    spa = blockReduceSum(spa, sh);
    float np = sqrtf(sp2);
    float n = fmaxf(np, 1e-15f);
    float f = tanhf(SQC * n) / (SQC * n);
    float x2 = f * f * sp2;
    float conf = 1.f - CURV * x2;
    float anorm = fabsf(conf) * sqrtf(sa2);
    float kkv = (2.f / conf) * anorm / SQC;
    float pa = f * conf * spa;
#pragma unroll
    for (int r = 0; r < 4; r++) {
        int i = tid + r * 256;
        g_pp[(size_t)c * ND + i] = f * pr[i];
        g_ap[(size_t)c * ND + i] = conf * ar[i];
    }
    if (tid == 0) {
        g_cs[c] = x2; g_cs[NC + c] = anorm; g_cs[2 * NC + c] = kkv; g_cs[3 * NC + c] = pa;
    }
}

// ---------------- 7) fused maps + hyperbolic MLR logits ----------------
__global__ void k_logits(float* __restrict__ dout) {
    int b = blockIdx.x;
    const float* oh = dout + OH_OFF + (size_t)b * ND;
    __shared__ float sy[ND];
    __shared__ float sh[33];
    int tid = threadIdx.x;
    float acc = 0.f;
#pragma unroll
    for (int r = 0; r < 4; r++) {
        int i = tid + r * 256;
        float v = oh[i];
        sy[i] = v;
        acc += v * v;
    }
    float r2 = blockReduceSum(acc, sh);
    float rn = sqrtf(r2);
    float rc = SQC * rn;
    float g1 = asinhf(rc) / fmaxf(rc, EPSF);
    float nu = fmaxf(g1 * rn, 1e-15f);
    float f2 = tanhf(SQC * nu) / (SQC * nu);
    float nw = f2 * (g1 * rn);
    float maxn = (1.f - 0.004f) / SQC;
    float n3 = fmaxf(nw, 1e-15f);
    float scale = (n3 > maxn) ? (maxn / n3) : 1.f;
    float s = g1 * f2 * scale;
    float y2 = s * s * r2;

    int w = tid >> 5, lane = tid & 31;
    for (int c = w; c < NC; c += 8) {
        const float* pp = g_pp + (size_t)c * ND;
        const float* ap = g_ap + (size_t)c * ND;
        float dp = 0.f, da = 0.f;
        for (int i = lane; i < ND; i += 32) {
            float v = sy[i];
            dp += v * pp[i];
            da += v * ap[i];
        }
#pragma unroll
        for (int o = 16; o > 0; o >>= 1) {
            dp += __shfl_down_sync(0xffffffffu, dp, o);
            da += __shfl_down_sync(0xffffffffu, da, o);
        }
        if (lane == 0) {
            float x2 = g_cs[c], anorm = g_cs[NC + c], kkv = g_cs[2 * NC + c], pa = g_cs[3 * NC + c];
            float xy = -s * dp;
            float ya = s * da;
            float A  = 1.f + 2.f * CURV * xy + CURV * y2;
            float Bc = 1.f - CURV * x2;
            float den0 = 1.f + 2.f * CURV * xy + CURV * CURV * x2 * y2 + 1e-5f;
            float mobdot = (A * (-pa) + Bc * ya) / den0;
            float num2 = 2.f * SQC * mobdot;
            float mob2 = (A * A * x2 + Bc * Bc * y2 + 2.f * A * Bc * xy) / (den0 * den0);
            float den2 = anorm * (1.f - CURV * mob2);
            dout[(size_t)b * NC + c] = kkv * asinhf(num2 / den2);
        }
    }
}

// ---------------- launch ----------------
extern "C" void kernel_launch(void* const* d_in, const int* in_sizes, int n_in,
                              void* d_out, int out_size) {
    const float* order_hyp  = (const float*)d_in[0];
    const float* family_hyp = (const float*)d_in[1];
    const float* order_euc  = (const float*)d_in[2];
    const float* family_euc = (const float*)d_in[3];
    const float* order      = (const float*)d_in[4];
    const float* family     = (const float*)d_in[5];
    const int*   mask       = (const int*)  d_in[6];
    const float* in_proj_w  = (const float*)d_in[7];
    const float* in_proj_b  = (const float*)d_in[8];
    const float* out_proj_w = (const float*)d_in[9];
    const float* out_proj_b = (const float*)d_in[10];
    const float* ln_w       = (const float*)d_in[11];
    const float* ln_b       = (const float*)d_in[12];
    const float* to_w       = (const float*)d_in[13];
    const float* to_b       = (const float*)d_in[14];
    const float* tf_w       = (const float*)d_in[15];
    const float* tf_b       = (const float*)d_in[16];
    const float* mlr_a      = (const float*)d_in[17];
    const float* mlr_p      = (const float*)d_in[18];
    float* out = (float*)d_out;

    float *p_qkv, *p_ctx, *p_attn, *p_uo, *p_uf;
    __nv_bfloat16 *p_a3, *p_w3;
    cudaGetSymbolAddress((void**)&p_qkv,  g_qkv);
    cudaGetSymbolAddress((void**)&p_ctx,  g_ctx);
    cudaGetSymbolAddress((void**)&p_attn, g_attn);
    cudaGetSymbolAddress((void**)&p_uo,   g_uo);
    cudaGetSymbolAddress((void**)&p_uf,   g_uf);
    cudaGetSymbolAddress((void**)&p_a3,   g_a3);
    cudaGetSymbolAddress((void**)&p_w3,   g_w3);

    cudaFuncSetAttribute(k_gemm_mma, cudaFuncAttributeMaxDynamicSharedMemorySize, SMEM_GEMM);

    // weight splits (hi | lo | hi)
    k_cvt3<<<dim3(ND / 256, 3 * ND), 256>>>(in_proj_w,  p_w3 + W_IN3_OFF,  ND, 1);
    k_cvt3<<<dim3(ND / 256, ND),     256>>>(out_proj_w, p_w3 + W_OUT3_OFF, ND, 1);
    k_cvt3<<<dim3(NT / 256, ND),     256>>>(to_w,       p_w3 + W_TO3_OFF,  NT, 1);
    k_cvt3<<<dim3(NT / 256, ND),     256>>>(tf_w,       p_w3 + W_TF3_OFF,  NT, 1);

    // 1) stacked features (fp32 residual + split-bf16 activation)
    k_prep_gf<<<dim3(NB, NS), 256>>>(order_hyp, family_hyp, order_euc, family_euc);

    // 2) QKV: [16384,3072] = gf0_3[16384,3072] @ w_in3[3072,3072]^T + bias
    k_gemm_mma<<<dim3(3 * ND / 128, NB * NS / 128), 256, SMEM_GEMM>>>(
        p_a3, p_w3 + W_IN3_OFF, in_proj_b, p_qkv, NB * NS, 3 * ND, 3 * ND);

    // 3) attention
    k_attn<<<NB * NH, HD>>>();

    // 4) ctx split, then out-proj
    k_cvt3<<<dim3(ND / 256, NB * NS), 256>>>(p_ctx, p_a3, ND, 0);
    k_gemm_mma<<<dim3(ND / 128, NB * NS / 128), 256, SMEM_GEMM>>>(
        p_a3, p_w3 + W_OUT3_OFF, out_proj_b, p_attn, NB * NS, ND, 3 * ND);

    // 5) layernorm + l_expmap0 -> d_out
    k_ln_map<<<dim3(NB, NS), 256>>>(ln_w, ln_b, out);

    // 6) text projections
    k_cvt3<<<dim3(NT / 256, NB), 256>>>(order,  p_a3, NT, 0);
    k_cvt3<<<dim3(NT / 256, NB), 256>>>(family, p_a3 + FAM3_OFF, NT, 0);
    k_gemm_mma<<<dim3(ND / 128, NB / 128), 256, SMEM_GEMM>>>(
        p_a3, p_w3 + W_TO3_OFF, to_b, p_uo, NB, ND, 3 * NT);
    k_gemm_mma<<<dim3(ND / 128, NB / 128), 256, SMEM_GEMM>>>(
        p_a3 + FAM3_OFF, p_w3 + W_TF3_OFF, tf_b, p_uf, NB, ND, 3 * NT);

    // 7) penalties + loss
    k_pen<<<dim3(NB, 2), 256>>>(out);
    k_loss<<<1, 1024>>>(mask, out);

    // 8) MLR constants + logits
    k_cls<<<NC, 256>>>(mlr_a, mlr_p);
    k_logits<<<NB, 256>>>(out);
}

// round 15
// speedup vs baseline: 1.0530x; 1.0530x over previous
#include <cuda_runtime.h>
#include <cuda_bf16.h>
#include <math.h>
#include <stdint.h>

// ---------------- problem constants ----------------
constexpr int NB = 4096;   // batch
constexpr int ND = 1024;   // model dim
constexpr int NT = 768;    // text dim
constexpr int NC = 16;     // classes
constexpr int NH = 4;      // heads
constexpr int NS = 4;      // sequence length of stacked features
constexpr int HD = ND / NH; // 256

#define CURV 0.05f
#define SQC  0.22360679774997896f       // sqrt(0.05)
#define EPSF 1e-8f
#define ASINH_MAX 11.090354888959125f   // arcsinh(2^15)

// output layout (flattened tuple: logits, loss, oh, fh, oeu, feu)
constexpr long long LOSS_OFF = (long long)NB * NC;
constexpr long long OH_OFF   = LOSS_OFF + 1;
constexpr long long FH_OFF   = OH_OFF  + (long long)NB * ND;
constexpr long long OEU_OFF  = FH_OFF  + (long long)NB * ND;
constexpr long long FEU_OFF  = OEU_OFF + (long long)NB * ND;

// ---------------- device scratch ----------------
__device__ float g_gf0 [(size_t)NB * NS * ND];
__device__ float g_qkv [(size_t)NB * NS * 3 * ND];
__device__ float g_attn[(size_t)NB * NS * ND];
__device__ float g_uo  [(size_t)NB * ND];
__device__ float g_uf  [(size_t)NB * ND];
__device__ float g_pen [2 * NB];
__device__ float g_pp  [NC * ND];
__device__ float g_ap  [NC * ND];
__device__ float g_cs  [4 * NC];

// split-bf16 staging: activations (reused: gf0_3 -> ctx3 -> order3+family3)
__device__ __nv_bfloat16 g_a3[(size_t)NB * NS * 3 * ND];
// weights, split-bf16
constexpr size_t W_IN3_OFF  = 0;                                      // 3072 x 3072
constexpr size_t W_OUT3_OFF = W_IN3_OFF  + (size_t)3 * ND * 3 * ND;   // 1024 x 3072
constexpr size_t W_TO3_OFF  = W_OUT3_OFF + (size_t)ND * 3 * ND;       // 1024 x 2304
constexpr size_t W_TF3_OFF  = W_TO3_OFF  + (size_t)ND * 3 * NT;
__device__ __nv_bfloat16 g_w3[W_TF3_OFF + (size_t)ND * 3 * NT];
constexpr size_t FAM3_OFF = (size_t)NB * 3 * NT;

// ---------------- small helpers ----------------
__device__ __forceinline__ float blockReduceSum(float v, volatile float* sh) {
    int lane = threadIdx.x & 31, wid = threadIdx.x >> 5;
#pragma unroll
    for (int o = 16; o > 0; o >>= 1) v += __shfl_down_sync(0xffffffffu, v, o);
    if (lane == 0) sh[wid] = v;
    __syncthreads();
    if (wid == 0) {
        int nw = (blockDim.x + 31) >> 5;
        float t = (lane < nw) ? sh[lane] : 0.f;
#pragma unroll
        for (int o = 16; o > 0; o >>= 1) t += __shfl_down_sync(0xffffffffu, t, o);
        if (lane == 0) sh[32] = t;
    }
    __syncthreads();
    float r = sh[32];
    __syncthreads();
    return r;
}

__device__ __forceinline__ uint32_t smem_u32(const void* p) {
    uint32_t a;
    asm("{ .reg .u64 t; cvta.to.shared.u64 t, %1; cvt.u32.u64 %0, t; }" : "=r"(a) : "l"(p));
    return a;
}

#define SWZ(o) ((o) ^ (((o) >> 3) & 0x70))

__device__ __forceinline__ void cp16(uint32_t dst, const void* src) {
    asm volatile("cp.async.cg.shared.global [%0], [%1], 16;" :: "r"(dst), "l"(src));
}
__device__ __forceinline__ void cp_commit() {
    asm volatile("cp.async.commit_group;" ::: "memory");
}
__device__ __forceinline__ void cp_wait1() {
    asm volatile("cp.async.wait_group 1;" ::: "memory");
}
__device__ __forceinline__ void ldm4(uint32_t* r, uint32_t a) {
    asm volatile("ldmatrix.sync.aligned.m8n8.x4.shared.b16 {%0,%1,%2,%3}, [%4];"
                 : "=r"(r[0]), "=r"(r[1]), "=r"(r[2]), "=r"(r[3]) : "r"(a));
}
__device__ __forceinline__ void mma16816(float* d, const uint32_t* a, uint32_t b0, uint32_t b1) {
    asm volatile(
        "mma.sync.aligned.m16n8k16.row.col.f32.bf16.bf16.f32 "
        "{%0,%1,%2,%3},{%4,%5,%6,%7},{%8,%9},{%0,%1,%2,%3};"
        : "+f"(d[0]), "+f"(d[1]), "+f"(d[2]), "+f"(d[3])
        : "r"(a[0]), "r"(a[1]), "r"(a[2]), "r"(a[3]), "r"(b0), "r"(b1));
}

// ---------------- mma.sync GEMM: C[M,N] = A[M,K3] @ B[N,K3]^T + bias ----------------
// 128x128 tile, BK=64 bf16 (128B rows, SW128 swizzle), 3-stage cp.async pipeline
constexpr uint32_t AB_STAGE  = 128 * 128;      // 16 KB per operand per stage
constexpr uint32_t STAGE_B   = 2 * AB_STAGE;   // 32 KB
constexpr int      STAGES    = 3;
constexpr uint32_t SMEM_GEMM = STAGES * STAGE_B;   // 96 KB

__device__ __forceinline__ void load_stage(uint32_t sb, int s,
                                           const __nv_bfloat16* Ab, const __nv_bfloat16* Bb,
                                           int K3, int kt, int tid) {
    uint32_t aS = sb + (uint32_t)s * STAGE_B;
    uint32_t bS = aS + AB_STAGE;
    const __nv_bfloat16* Ap = Ab + (size_t)kt * 64;
    const __nv_bfloat16* Bp = Bb + (size_t)kt * 64;
#pragma unroll
    for (int u = 0; u < 4; u++) {
        int id = tid + u * 256;
        int row = id >> 3, ch = id & 7;
        uint32_t o = SWZ((uint32_t)row * 128 + ch * 16);
        cp16(aS + o, Ap + (size_t)row * K3 + ch * 8);
        cp16(bS + o, Bp + (size_t)row * K3 + ch * 8);
    }
    cp_commit();
}

__global__ __launch_bounds__(256, 2)
void k_gemm_mma(const __nv_bfloat16* __restrict__ A, const __nv_bfloat16* __restrict__ B,
                const float* __restrict__ bias, float* __restrict__ C,
                int M, int N, int K3) {
    extern __shared__ char smem[];
    uint32_t sb = smem_u32(smem);
    int tid = threadIdx.x, wid = tid >> 5, lane = tid & 31;
    int wm = wid >> 1, wn = wid & 1;           // 4x2 warp grid
    int lr = lane & 7, mi = lane >> 3;

    int bm = blockIdx.y * 128;
    int bn = blockIdx.x * 128;
    const __nv_bfloat16* Ab = A + (size_t)bm * K3;
    const __nv_bfloat16* Bb = B + (size_t)bn * K3;
    const int NK = K3 >> 6;

    // per-lane ldmatrix address precompute
    int aR = wm * 32 + lr + (mi & 1) * 8;      // + i*16 per m-atom
    uint32_t aKh = (uint32_t)(mi >> 1) * 16;
    uint32_t xa = (uint32_t)(aR & 7) * 16;
    uint32_t aOff0 = (uint32_t)aR * 128;
    uint32_t aOff1 = aOff0 + 16 * 128;
    int bR = wn * 64 + lr + (mi >> 1) * 8;     // + j2*16 per n-atom-pair
    uint32_t bKh = (uint32_t)(mi & 1) * 16;
    uint32_t xb = (uint32_t)(bR & 7) * 16;
    uint32_t bOff[4];
#pragma unroll
    for (int j2 = 0; j2 < 4; j2++) bOff[j2] = (uint32_t)(bR + j2 * 16) * 128;

    float acc[2][8][4];
#pragma unroll
    for (int i = 0; i < 2; i++)
#pragma unroll
        for (int j = 0; j < 8; j++)
#pragma unroll
            for (int r = 0; r < 4; r++) acc[i][j][r] = 0.f;

    load_stage(sb, 0, Ab, Bb, K3, 0, tid);
    load_stage(sb, 1, Ab, Bb, K3, 1, tid);

    for (int kt = 0; kt < NK; kt++) {
        cp_wait1();
        __syncthreads();
        // issue next stage's loads FIRST so they overlap the MMA burst below;
        // buffer (kt+2)%3 == (kt-1)%3 was fully consumed before the sync above.
        if (kt + 2 < NK) load_stage(sb, (kt + 2) % STAGES, Ab, Bb, K3, kt + 2, tid);
        else cp_commit();

        int s = kt % STAGES;
        uint32_t aS = sb + (uint32_t)s * STAGE_B;
        uint32_t bS = aS + AB_STAGE;
#pragma unroll
        for (int ks = 0; ks < 4; ks++) {
            uint32_t kb = (uint32_t)ks * 32;
            uint32_t afrag[2][4];
            ldm4(afrag[0], aS + aOff0 + ((kb + aKh) ^ xa));
            ldm4(afrag[1], aS + aOff1 + ((kb + aKh) ^ xa));
            uint32_t bfrag[4][4];
#pragma unroll
            for (int j2 = 0; j2 < 4; j2++)
                ldm4(bfrag[j2], bS + bOff[j2] + ((kb + bKh) ^ xb));
#pragma unroll
            for (int i = 0; i < 2; i++)
#pragma unroll
                for (int j = 0; j < 8; j++)
                    mma16816(acc[i][j], afrag[i],
                             bfrag[j >> 1][(j & 1) * 2], bfrag[j >> 1][(j & 1) * 2 + 1]);
        }
    }

    // epilogue: direct float2 stores with bias
    int mBase = bm + wm * 32 + (lane >> 2);
    int nBase = bn + wn * 64 + 2 * (lane & 3);
#pragma unroll
    for (int i = 0; i < 2; i++) {
        int m0 = mBase + i * 16;
#pragma unroll
        for (int j = 0; j < 8; j++) {
            int n = nBase + j * 8;
            float bx = bias[n], by = bias[n + 1];
            float2 v0 = { acc[i][j][0] + bx, acc[i][j][1] + by };
            float2 v1 = { acc[i][j][2] + bx, acc[i][j][3] + by };
            *(float2*)(C + (size_t)m0 * N + n) = v0;
            *(float2*)(C + (size_t)(m0 + 8) * N + n) = v1;
        }
    }
}

// ---------------- split-bf16 converter ----------------
// weightMode=0 (activation): [hi | hi | lo];  weightMode=1 (weight): [hi | lo | hi]
__global__ void k_cvt3(const float* __restrict__ src, __nv_bfloat16* __restrict__ dst,
                       int K, int weightMode) {
    int r = blockIdx.y;
    int k = blockIdx.x * 256 + threadIdx.x;
    float x = src[(size_t)r * K + k];
    __nv_bfloat16 hi = __float2bfloat16(x);
    __nv_bfloat16 lo = __float2bfloat16(x - __bfloat162float(hi));
    size_t b3 = (size_t)r * 3 * K;
    dst[b3 + k] = hi;
    dst[b3 + K + k]     = weightMode ? lo : hi;
    dst[b3 + 2 * K + k] = weightMode ? hi : lo;
}

// ---------------- 1) gf0 = stack(p_logmap0(oh), p_logmap0(fh), oeu, feu) + split ----------------
__global__ void k_prep_gf(const float* __restrict__ ohy, const float* __restrict__ fhy,
                          const float* __restrict__ oeu, const float* __restrict__ feu) {
    int b = blockIdx.x, s = blockIdx.y;
    const float* src = (s == 0) ? ohy : (s == 1) ? fhy : (s == 2) ? oeu : feu;
    src += (size_t)b * ND;
    size_t row = (size_t)b * NS + s;
    float* dst = g_gf0 + row * ND;
    __nv_bfloat16* d3 = g_a3 + row * 3 * ND;
    __shared__ float sh[33];
    float f = 1.f;
    if (s < 2) {
        float acc = 0.f;
        for (int i = threadIdx.x; i < ND; i += blockDim.x) { float v = src[i]; acc += v * v; }
        float n2 = blockReduceSum(acc, sh);
        float n = fmaxf(sqrtf(n2), 1e-15f);
        float t = fminf(SQC * n, 1.f - 1e-5f);
        float art = 0.5f * (log1pf(t) - log1pf(-t));
        f = art / (n * SQC);
    }
    for (int i = threadIdx.x; i < ND; i += blockDim.x) {
        float v = src[i] * f;
        dst[i] = v;
        __nv_bfloat16 hi = __float2bfloat16(v);
        __nv_bfloat16 lo = __float2bfloat16(v - __bfloat162float(hi));
        d3[i] = hi; d3[ND + i] = hi; d3[2 * ND + i] = lo;
    }
}

// ---------------- 2) attention (writes context directly as split-bf16 [hi|hi|lo]) ----------------
__global__ void k_attn() {
    int bh = blockIdx.x;
    int b = bh >> 2, h = bh & 3;
    __shared__ float q[NS][HD], kk[NS][HD], v[NS][HD];
    __shared__ float sc[NS][NS];
    int tid = threadIdx.x;
    const float* base = g_qkv + (size_t)b * NS * 3 * ND;
#pragma unroll
    for (int si = 0; si < NS; si++) {
        q [si][tid] = base[si * 3 * ND +          h * HD + tid];
        kk[si][tid] = base[si * 3 * ND + ND     + h * HD + tid];
        v [si][tid] = base[si * 3 * ND + 2 * ND + h * HD + tid];
    }
    __syncthreads();
    int w = tid >> 5, lane = tid & 31;
    for (int p = w; p < 16; p += 8) {
        int i = p >> 2, j = p & 3;
        float s = 0.f;
        for (int d = lane; d < HD; d += 32) s += q[i][d] * kk[j][d];
#pragma unroll
        for (int o = 16; o > 0; o >>= 1) s += __shfl_down_sync(0xffffffffu, s, o);
        if (lane == 0) sc[i][j] = s * 0.0625f;
    }
    __syncthreads();
    if (tid < 4) {
        float s0 = sc[tid][0], s1 = sc[tid][1], s2 = sc[tid][2], s3 = sc[tid][3];
        float m = fmaxf(fmaxf(s0, s1), fmaxf(s2, s3));
        float e0 = expf(s0 - m), e1 = expf(s1 - m), e2 = expf(s2 - m), e3 = expf(s3 - m);
        float inv = 1.f / (e0 + e1 + e2 + e3);
        sc[tid][0] = e0 * inv; sc[tid][1] = e1 * inv; sc[tid][2] = e2 * inv; sc[tid][3] = e3 * inv;
    }
    __syncthreads();
#pragma unroll
    for (int i = 0; i < NS; i++) {
        float o = sc[i][0] * v[0][tid] + sc[i][1] * v[1][tid] + sc[i][2] * v[2][tid] + sc[i][3] * v[3][tid];
        size_t row = (size_t)b * NS + i;
        int col = h * HD + tid;
        __nv_bfloat16 hi = __float2bfloat16(o);
        __nv_bfloat16 lo = __float2bfloat16(o - __bfloat162float(hi));
        __nv_bfloat16* d3 = g_a3 + row * 3 * ND;
        d3[col] = hi; d3[ND + col] = hi; d3[2 * ND + col] = lo;
    }
}

// ---------------- 3) layernorm + l_expmap0 ----------------
__global__ void k_ln_map(const float* __restrict__ ln_w, const float* __restrict__ ln_b,
                         float* __restrict__ dout) {
    int b = blockIdx.x, s = blockIdx.y;
    size_t off = ((size_t)b * NS + s) * ND;
    __shared__ float sh[33];
    int tid = threadIdx.x;
    float x[4];
    float sum = 0.f;
#pragma unroll
    for (int r = 0; r < 4; r++) {
        int i = tid + r * 256;
        x[r] = g_gf0[off + i] + g_attn[off + i];
        sum += x[r];
    }
    float mu = blockReduceSum(sum, sh) * (1.f / ND);
    float vs = 0.f;
#pragma unroll
    for (int r = 0; r < 4; r++) { float d = x[r] - mu; vs += d * d; }
    float var = blockReduceSum(vs, sh) * (1.f / ND);
    float rstd = rsqrtf(var + 1e-5f);
    float y[4];
#pragma unroll
    for (int r = 0; r < 4; r++) {
        int i = tid + r * 256;
        y[r] = (x[r] - mu) * rstd * ln_w[i] + ln_b[i];
    }
    long long base = (s == 0) ? OH_OFF : (s == 1) ? FH_OFF : (s == 2) ? OEU_OFF : FEU_OFF;
    float* dst = dout + base + (size_t)b * ND;
    if (s < 2) {
        float n2acc = 0.f;
#pragma unroll
        for (int r = 0; r < 4; r++) n2acc += y[r] * y[r];
        float n2 = blockReduceSum(n2acc, sh);
        float rc = SQC * sqrtf(n2);
        float si = fminf(fmaxf(rc, EPSF), ASINH_MAX);
        float f = sinhf(si) / fmaxf(rc, EPSF);
#pragma unroll
        for (int r = 0; r < 4; r++) dst[tid + r * 256] = y[r] * f;
    } else {
#pragma unroll
        for (int r = 0; r < 4; r++) dst[tid + r * 256] = y[r];
    }
}

// ---------------- 4) entailment penalties ----------------
__global__ void k_pen(const float* __restrict__ dout) {
    int b = blockIdx.x, which = blockIdx.y;
    const float* u = (which ? g_uf : g_uo) + (size_t)b * ND;
    const float* y = dout + (which ? OH_OFF : FH_OFF) + (size_t)b * ND;
    __shared__ float sh[33];
    int tid = threadIdx.x;
    float su2 = 0.f, suy = 0.f, sy2 = 0.f;
#pragma unroll
    for (int r = 0; r < 4; r++) {
        int i = tid + r * 256;
        float uu = u[i], yy = y[i];
        su2 += uu * uu; suy += uu * yy; sy2 += yy * yy;
    }
    su2 = blockReduceSum(su2, sh);
    suy = blockReduceSum(suy, sh);
    sy2 = blockReduceSum(sy2, sh);
    if (tid == 0) {
        float ru = sqrtf(su2);
        float rc = SQC * ru;
        float si = fminf(fmaxf(rc, EPSF), ASINH_MAX);
        float f = sinhf(si) / fmaxf(rc, EPSF);
        float xx = f * f * su2;
        float xy = f * suy;
        float yy = sy2;
        float nx = f * ru;
        float xt = sqrtf(1.f / CURV + xx);
        float yt = sqrtf(1.f / CURV + yy);
        float cxy = CURV * (xy - xt * yt);
        float num = yt + cxy * xt;
        float den = sqrtf(fmaxf(cxy * cxy - 1.f, EPSF));
        float acos_in = num / (nx * den + EPSF);
        acos_in = fminf(fmaxf(acos_in, -1.f + EPSF), 1.f - EPSF);
        float angle = acosf(acos_in);
        float asin_in = 0.2f / (nx * SQC + EPSF);
        asin_in = fminf(fmaxf(asin_in, -1.f + EPSF), 1.f - EPSF);
        float ap = asinf(asin_in);
        g_pen[which * NB + b] = fmaxf(angle - ap, 0.f);
    }
}

// ---------------- 5) loss reduction ----------------
__global__ void k_loss(const int* __restrict__ mask, float* __restrict__ dout) {
    __shared__ float sh[33];
    int tid = threadIdx.x;
    float so = 0.f, sf = 0.f, cnt = 0.f;
    for (int i = tid; i < NB; i += blockDim.x) {
        so += g_pen[i];
        float m = (float)mask[i];
        sf += g_pen[NB + i] * m;
        cnt += m;
    }
    so = blockReduceSum(so, sh);
    sf = blockReduceSum(sf, sh);
    cnt = blockReduceSum(cnt, sh);
    if (tid == 0) {
        float ol = so * (1.f / NB);
        float fl = (cnt > 0.f) ? sf / fmaxf(cnt, 1.f) : 0.f;
        dout[LOSS_OFF] = ol + fl;
    }
}

// ---------------- 6) per-class MLR constants ----------------
__global__ void k_cls(const float* __restrict__ a, const float* __restrict__ p) {
    int c = blockIdx.x;
    const float* pr = p + (size_t)c * ND;
    const float* ar = a + (size_t)c * ND;
    __shared__ float sh[33];
    int tid = threadIdx.x;
    float sp2 = 0.f, sa2 = 0.f, spa = 0.f;
#pragma unroll
    for (int r = 0; r < 4; r++) {
        int i = tid + r * 256;
        float pv = pr[i], av = ar[i];
        sp2 += pv * pv; sa2 += av * av; spa += pv * av;
    }
    sp2 = blockReduceSum(sp2, sh);
    sa2 = blockReduceSum(sa2, sh);
    spa = blockReduceSum(spa, sh);
    float np = sqrtf(sp2);
    float n = fmaxf(np, 1e-15f);
    float f = tanhf(SQC * n) / (SQC * n);
    float x2 = f * f * sp2;
    float conf = 1.f - CURV * x2;
    float anorm = fabsf(conf) * sqrtf(sa2);
    float kkv = (2.f / conf) * anorm / SQC;
    float pa = f * conf * spa;
#pragma unroll
    for (int r = 0; r < 4; r++) {
        int i = tid + r * 256;
        g_pp[(size_t)c * ND + i] = f * pr[i];
        g_ap[(size_t)c * ND + i] = conf * ar[i];
    }
    if (tid == 0) {
        g_cs[c] = x2; g_cs[NC + c] = anorm; g_cs[2 * NC + c] = kkv; g_cs[3 * NC + c] = pa;
    }
}

// ---------------- 7) fused maps + hyperbolic MLR logits ----------------
__global__ void k_logits(float* __restrict__ dout) {
    int b = blockIdx.x;
    const float* oh = dout + OH_OFF + (size_t)b * ND;
    __shared__ float sy[ND];
    __shared__ float sh[33];
    int tid = threadIdx.x;
    float acc = 0.f;
#pragma unroll
    for (int r = 0; r < 4; r++) {
        int i = tid + r * 256;
        float v = oh[i];
        sy[i] = v;
        acc += v * v;
    }
    float r2 = blockReduceSum(acc, sh);
    float rn = sqrtf(r2);
    float rc = SQC * rn;
    float g1 = asinhf(rc) / fmaxf(rc, EPSF);
    float nu = fmaxf(g1 * rn, 1e-15f);
    float f2 = tanhf(SQC * nu) / (SQC * nu);
    float nw = f2 * (g1 * rn);
    float maxn = (1.f - 0.004f) / SQC;
    float n3 = fmaxf(nw, 1e-15f);
    float scale = (n3 > maxn) ? (maxn / n3) : 1.f;
    float s = g1 * f2 * scale;
    float y2 = s * s * r2;

    int w = tid >> 5, lane = tid & 31;
    for (int c = w; c < NC; c += 8) {
        const float* pp = g_pp + (size_t)c * ND;
        const float* ap = g_ap + (size_t)c * ND;
        float dp = 0.f, da = 0.f;
        for (int i = lane; i < ND; i += 32) {
            float v = sy[i];
            dp += v * pp[i];
            da += v * ap[i];
        }
#pragma unroll
        for (int o = 16; o > 0; o >>= 1) {
            dp += __shfl_down_sync(0xffffffffu, dp, o);
            da += __shfl_down_sync(0xffffffffu, da, o);
        }
        if (lane == 0) {
            float x2 = g_cs[c], anorm = g_cs[NC + c], kkv = g_cs[2 * NC + c], pa = g_cs[3 * NC + c];
            float xy = -s * dp;
            float ya = s * da;
            float A  = 1.f + 2.f * CURV * xy + CURV * y2;
            float Bc = 1.f - CURV * x2;
            float den0 = 1.f + 2.f * CURV * xy + CURV * CURV * x2 * y2 + 1e-5f;
            float mobdot = (A * (-pa) + Bc * ya) / den0;
            float num2 = 2.f * SQC * mobdot;
            float mob2 = (A * A * x2 + Bc * Bc * y2 + 2.f * A * Bc * xy) / (den0 * den0);
            float den2 = anorm * (1.f - CURV * mob2);
            dout[(size_t)b * NC + c] = kkv * asinhf(num2 / den2);
        }
    }
}

// ---------------- launch ----------------
extern "C" void kernel_launch(void* const* d_in, const int* in_sizes, int n_in,
                              void* d_out, int out_size) {
    const float* order_hyp  = (const float*)d_in[0];
    const float* family_hyp = (const float*)d_in[1];
    const float* order_euc  = (const float*)d_in[2];
    const float* family_euc = (const float*)d_in[3];
    const float* order      = (const float*)d_in[4];
    const float* family     = (const float*)d_in[5];
    const int*   mask       = (const int*)  d_in[6];
    const float* in_proj_w  = (const float*)d_in[7];
    const float* in_proj_b  = (const float*)d_in[8];
    const float* out_proj_w = (const float*)d_in[9];
    const float* out_proj_b = (const float*)d_in[10];
    const float* ln_w       = (const float*)d_in[11];
    const float* ln_b       = (const float*)d_in[12];
    const float* to_w       = (const float*)d_in[13];
    const float* to_b       = (const float*)d_in[14];
    const float* tf_w       = (const float*)d_in[15];
    const float* tf_b       = (const float*)d_in[16];
    const float* mlr_a      = (const float*)d_in[17];
    const float* mlr_p      = (const float*)d_in[18];
    float* out = (float*)d_out;

    float *p_qkv, *p_attn, *p_uo, *p_uf;
    __nv_bfloat16 *p_a3, *p_w3;
    cudaGetSymbolAddress((void**)&p_qkv,  g_qkv);
    cudaGetSymbolAddress((void**)&p_attn, g_attn);
    cudaGetSymbolAddress((void**)&p_uo,   g_uo);
    cudaGetSymbolAddress((void**)&p_uf,   g_uf);
    cudaGetSymbolAddress((void**)&p_a3,   g_a3);
    cudaGetSymbolAddress((void**)&p_w3,   g_w3);

    cudaFuncSetAttribute(k_gemm_mma, cudaFuncAttributeMaxDynamicSharedMemorySize, SMEM_GEMM);

    // weight splits (hi | lo | hi)
    k_cvt3<<<dim3(ND / 256, 3 * ND), 256>>>(in_proj_w,  p_w3 + W_IN3_OFF,  ND, 1);
    k_cvt3<<<dim3(ND / 256, ND),     256>>>(out_proj_w, p_w3 + W_OUT3_OFF, ND, 1);
    k_cvt3<<<dim3(NT / 256, ND),     256>>>(to_w,       p_w3 + W_TO3_OFF,  NT, 1);
    k_cvt3<<<dim3(NT / 256, ND),     256>>>(tf_w,       p_w3 + W_TF3_OFF,  NT, 1);

    // 1) stacked features (fp32 residual + split-bf16 activation)
    k_prep_gf<<<dim3(NB, NS), 256>>>(order_hyp, family_hyp, order_euc, family_euc);

    // 2) QKV: [16384,3072] = gf0_3[16384,3072] @ w_in3[3072,3072]^T + bias
    k_gemm_mma<<<dim3(3 * ND / 128, NB * NS / 128), 256, SMEM_GEMM>>>(
        p_a3, p_w3 + W_IN3_OFF, in_proj_b, p_qkv, NB * NS, 3 * ND, 3 * ND);

    // 3) attention (writes ctx split-bf16 into g_a3 directly)
    k_attn<<<NB * NH, HD>>>();

    // 4) out-proj
    k_gemm_mma<<<dim3(ND / 128, NB * NS / 128), 256, SMEM_GEMM>>>(
        p_a3, p_w3 + W_OUT3_OFF, out_proj_b, p_attn, NB * NS, ND, 3 * ND);

    // 5) layernorm + l_expmap0 -> d_out
    k_ln_map<<<dim3(NB, NS), 256>>>(ln_w, ln_b, out);

    // 6) text projections
    k_cvt3<<<dim3(NT / 256, NB), 256>>>(order,  p_a3, NT, 0);
    k_cvt3<<<dim3(NT / 256, NB), 256>>>(family, p_a3 + FAM3_OFF, NT, 0);
    k_gemm_mma<<<dim3(ND / 128, NB / 128), 256, SMEM_GEMM>>>(
        p_a3, p_w3 + W_TO3_OFF, to_b, p_uo, NB, ND, 3 * NT);
    k_gemm_mma<<<dim3(ND / 128, NB / 128), 256, SMEM_GEMM>>>(
        p_a3 + FAM3_OFF, p_w3 + W_TF3_OFF, tf_b, p_uf, NB, ND, 3 * NT);

    // 7) penalties + loss
    k_pen<<<dim3(NB, 2), 256>>>(out);
    k_loss<<<1, 1024>>>(mask, out);

    // 8) MLR constants + logits
    k_cls<<<NC, 256>>>(mlr_a, mlr_p);
    k_logits<<<NB, 256>>>(out);
}

// round 16
// speedup vs baseline: 1.1165x; 1.0603x over previous
#include <cuda_runtime.h>
#include <cuda_bf16.h>
#include <math.h>
#include <stdint.h>

// ---------------- problem constants ----------------
constexpr int NB = 4096;   // batch
constexpr int ND = 1024;   // model dim
constexpr int NT = 768;    // text dim
constexpr int NC = 16;     // classes
constexpr int NH = 4;      // heads
constexpr int NS = 4;      // sequence length of stacked features
constexpr int HD = ND / NH; // 256

#define CURV 0.05f
#define SQC  0.22360679774997896f       // sqrt(0.05)
#define EPSF 1e-8f
#define ASINH_MAX 11.090354888959125f   // arcsinh(2^15)

// output layout (flattened tuple: logits, loss, oh, fh, oeu, feu)
constexpr long long LOSS_OFF = (long long)NB * NC;
constexpr long long OH_OFF   = LOSS_OFF + 1;
constexpr long long FH_OFF   = OH_OFF  + (long long)NB * ND;
constexpr long long OEU_OFF  = FH_OFF  + (long long)NB * ND;
constexpr long long FEU_OFF  = OEU_OFF + (long long)NB * ND;

// ---------------- device scratch ----------------
__device__ float g_gf0 [(size_t)NB * NS * ND];
__device__ float g_qkv [(size_t)NB * NS * 3 * ND];
__device__ float g_attn[(size_t)NB * NS * ND];
__device__ float g_uo  [(size_t)NB * ND];
__device__ float g_uf  [(size_t)NB * ND];
__device__ float g_pen [2 * NB];
__device__ float g_pp  [NC * ND];
__device__ float g_ap  [NC * ND];
__device__ float g_cs  [4 * NC];

// compact split-bf16 [hi | lo] (row length 2K)
__device__ __nv_bfloat16 g_a2[(size_t)NB * NS * 2 * ND];          // 64 MB (reused)
constexpr size_t W_IN2_OFF  = 0;                                   // 3072 rows x 2*1024
constexpr size_t W_OUT2_OFF = W_IN2_OFF  + (size_t)3 * ND * 2 * ND;
constexpr size_t W_TO2_OFF  = W_OUT2_OFF + (size_t)ND * 2 * ND;    // 1024 rows x 2*768
constexpr size_t W_TF2_OFF  = W_TO2_OFF  + (size_t)ND * 2 * NT;
__device__ __nv_bfloat16 g_w2[W_TF2_OFF + (size_t)ND * 2 * NT];
constexpr size_t FAM2_OFF = (size_t)NB * 2 * NT;

// ---------------- small helpers ----------------
__device__ __forceinline__ float blockReduceSum(float v, volatile float* sh) {
    int lane = threadIdx.x & 31, wid = threadIdx.x >> 5;
#pragma unroll
    for (int o = 16; o > 0; o >>= 1) v += __shfl_down_sync(0xffffffffu, v, o);
    if (lane == 0) sh[wid] = v;
    __syncthreads();
    if (wid == 0) {
        int nw = (blockDim.x + 31) >> 5;
        float t = (lane < nw) ? sh[lane] : 0.f;
#pragma unroll
        for (int o = 16; o > 0; o >>= 1) t += __shfl_down_sync(0xffffffffu, t, o);
        if (lane == 0) sh[32] = t;
    }
    __syncthreads();
    float r = sh[32];
    __syncthreads();
    return r;
}

__device__ __forceinline__ uint32_t smem_u32(const void* p) {
    uint32_t a;
    asm("{ .reg .u64 t; cvta.to.shared.u64 t, %1; cvt.u32.u64 %0, t; }" : "=r"(a) : "l"(p));
    return a;
}

// SW64 swizzle for 64-byte rows: bits [5:4] ^= bits [8:7]
#define SWZ64(o) ((o) ^ (((o) >> 3) & 0x30))

__device__ __forceinline__ void cp16(uint32_t dst, const void* src) {
    asm volatile("cp.async.cg.shared.global [%0], [%1], 16;" :: "r"(dst), "l"(src));
}
__device__ __forceinline__ void cp_commit() {
    asm volatile("cp.async.commit_group;" ::: "memory");
}
__device__ __forceinline__ void cp_wait1() {
    asm volatile("cp.async.wait_group 1;" ::: "memory");
}
__device__ __forceinline__ void ldm4(uint32_t* r, uint32_t a) {
    asm volatile("ldmatrix.sync.aligned.m8n8.x4.shared.b16 {%0,%1,%2,%3}, [%4];"
                 : "=r"(r[0]), "=r"(r[1]), "=r"(r[2]), "=r"(r[3]) : "r"(a));
}
__device__ __forceinline__ void mma16816(float* d, const uint32_t* a, uint32_t b0, uint32_t b1) {
    asm volatile(
        "mma.sync.aligned.m16n8k16.row.col.f32.bf16.bf16.f32 "
        "{%0,%1,%2,%3},{%4,%5,%6,%7},{%8,%9},{%0,%1,%2,%3};"
        : "+f"(d[0]), "+f"(d[1]), "+f"(d[2]), "+f"(d[3])
        : "r"(a[0]), "r"(a[1]), "r"(a[2]), "r"(a[3]), "r"(b0), "r"(b1));
}

// ---------------- split-GEMM: C = Ah*Bh^T + Al*Bh^T + Ah*Bl^T + bias ----------------
// A2 = [ah|al], B2 = [bh|bl] (row length 2K). Per 32-wide real-K chunk, load the
// 4 distinct tiles (Ah, Al, Bh, Bl; 128x32 bf16 = 8KB each, 64B rows SW64) and run
// 3 fragment-reusing MMA bursts.
constexpr uint32_t TILE4   = 128 * 64;          // 8 KB
constexpr uint32_t STAGE4  = 4 * TILE4;         // 32 KB
constexpr int      STAGES  = 3;
constexpr uint32_t SMEM_GEMM = STAGES * STAGE4; // 96 KB

__device__ __forceinline__ void load_stage4(uint32_t sb, int s,
                                            const __nv_bfloat16* Ab, const __nv_bfloat16* Bb,
                                            int K, int kc, int tid) {
    uint32_t st = sb + (uint32_t)s * STAGE4;
    int K2 = 2 * K;
#pragma unroll
    for (int u = 0; u < 8; u++) {
        int id = tid + u * 256;          // 0..2047
        int tile = id >> 9;              // 0:Ah 1:Al 2:Bh 3:Bl
        int w = id & 511;
        int row = w >> 2, ch = w & 3;
        uint32_t so = st + (uint32_t)tile * TILE4 + SWZ64((uint32_t)row * 64 + ch * 16);
        const __nv_bfloat16* base = (tile & 2) ? Bb : Ab;
        int col = kc * 32 + ch * 8 + ((tile & 1) ? K : 0);
        cp16(so, base + (size_t)row * K2 + col);
    }
    cp_commit();
}

__global__ __launch_bounds__(256, 2)
void k_gemm_mma(const __nv_bfloat16* __restrict__ A, const __nv_bfloat16* __restrict__ B,
                const float* __restrict__ bias, float* __restrict__ C,
                int M, int N, int K) {
    extern __shared__ char smem[];
    uint32_t sb = smem_u32(smem);
    int tid = threadIdx.x, wid = tid >> 5, lane = tid & 31;
    int wm = wid >> 1, wn = wid & 1;           // 4x2 warp grid
    int lr = lane & 7, mi = lane >> 3;

    int bm = blockIdx.y * 128;
    int bn = blockIdx.x * 128;
    const int K2 = 2 * K;
    const __nv_bfloat16* Ab = A + (size_t)bm * K2;
    const __nv_bfloat16* Bb = B + (size_t)bn * K2;
    const int NK = K >> 5;                      // 32 real-k per chunk

    // ldmatrix per-lane addresses (64B rows)
    int aR = wm * 32 + lr + (mi & 1) * 8;
    uint32_t aKh = (uint32_t)(mi >> 1) * 16;
    uint32_t xa = (uint32_t)((aR >> 1) & 3) * 16;
    uint32_t aOff0 = (uint32_t)aR * 64;
    uint32_t aOff1 = aOff0 + 16 * 64;
    int bR = wn * 64 + lr + (mi >> 1) * 8;
    uint32_t bKh = (uint32_t)(mi & 1) * 16;
    uint32_t xb = (uint32_t)((bR >> 1) & 3) * 16;
    uint32_t bOff[4];
#pragma unroll
    for (int j2 = 0; j2 < 4; j2++) bOff[j2] = (uint32_t)(bR + j2 * 16) * 64;

    float acc[2][8][4];
#pragma unroll
    for (int i = 0; i < 2; i++)
#pragma unroll
        for (int j = 0; j < 8; j++)
#pragma unroll
            for (int r = 0; r < 4; r++) acc[i][j][r] = 0.f;

    load_stage4(sb, 0, Ab, Bb, K, 0, tid);
    load_stage4(sb, 1, Ab, Bb, K, 1, tid);

    for (int kt = 0; kt < NK; kt++) {
        cp_wait1();
        __syncthreads();
        if (kt + 2 < NK) load_stage4(sb, (kt + 2) % STAGES, Ab, Bb, K, kt + 2, tid);
        else cp_commit();

        uint32_t st = sb + (uint32_t)(kt % STAGES) * STAGE4;
        uint32_t aH = st, aL = st + TILE4, bH = st + 2 * TILE4, bL = st + 3 * TILE4;
#pragma unroll
        for (int ks = 0; ks < 2; ks++) {
            uint32_t kb = (uint32_t)ks * 32;
            uint32_t aSel = (kb + aKh) ^ xa;
            uint32_t bSel = (kb + bKh) ^ xb;
            uint32_t ahf[2][4], alf[2][4], bf[4][4];
            // burst 1: Ah * Bh
            ldm4(ahf[0], aH + aOff0 + aSel);
            ldm4(ahf[1], aH + aOff1 + aSel);
#pragma unroll
            for (int j2 = 0; j2 < 4; j2++) ldm4(bf[j2], bH + bOff[j2] + bSel);
#pragma unroll
            for (int i = 0; i < 2; i++)
#pragma unroll
                for (int j = 0; j < 8; j++)
                    mma16816(acc[i][j], ahf[i], bf[j >> 1][(j & 1) * 2], bf[j >> 1][(j & 1) * 2 + 1]);
            // burst 2: Al * Bh (reuse Bh fragments)
            ldm4(alf[0], aL + aOff0 + aSel);
            ldm4(alf[1], aL + aOff1 + aSel);
#pragma unroll
            for (int i = 0; i < 2; i++)
#pragma unroll
                for (int j = 0; j < 8; j++)
                    mma16816(acc[i][j], alf[i], bf[j >> 1][(j & 1) * 2], bf[j >> 1][(j & 1) * 2 + 1]);
            // burst 3: Ah * Bl (reuse Ah fragments)
#pragma unroll
            for (int j2 = 0; j2 < 4; j2++) ldm4(bf[j2], bL + bOff[j2] + bSel);
#pragma unroll
            for (int i = 0; i < 2; i++)
#pragma unroll
                for (int j = 0; j < 8; j++)
                    mma16816(acc[i][j], ahf[i], bf[j >> 1][(j & 1) * 2], bf[j >> 1][(j & 1) * 2 + 1]);
        }
    }

    // epilogue: direct float2 stores with bias
    int mBase = bm + wm * 32 + (lane >> 2);
    int nBase = bn + wn * 64 + 2 * (lane & 3);
#pragma unroll
    for (int i = 0; i < 2; i++) {
        int m0 = mBase + i * 16;
#pragma unroll
        for (int j = 0; j < 8; j++) {
            int n = nBase + j * 8;
            float bx = bias[n], by = bias[n + 1];
            float2 v0 = { acc[i][j][0] + bx, acc[i][j][1] + by };
            float2 v1 = { acc[i][j][2] + bx, acc[i][j][3] + by };
            *(float2*)(C + (size_t)m0 * N + n) = v0;
            *(float2*)(C + (size_t)(m0 + 8) * N + n) = v1;
        }
    }
}

// ---------------- split-bf16 converter: [hi | lo] ----------------
__global__ void k_cvt2(const float* __restrict__ src, __nv_bfloat16* __restrict__ dst, int K) {
    int r = blockIdx.y;
    int k = blockIdx.x * 256 + threadIdx.x;
    float x = src[(size_t)r * K + k];
    __nv_bfloat16 hi = __float2bfloat16(x);
    __nv_bfloat16 lo = __float2bfloat16(x - __bfloat162float(hi));
    size_t b2 = (size_t)r * 2 * K;
    dst[b2 + k] = hi;
    dst[b2 + K + k] = lo;
}

// ---------------- 1) gf0 = stack(p_logmap0(oh), p_logmap0(fh), oeu, feu) + split ----------------
__global__ void k_prep_gf(const float* __restrict__ ohy, const float* __restrict__ fhy,
                          const float* __restrict__ oeu, const float* __restrict__ feu) {
    int b = blockIdx.x, s = blockIdx.y;
    const float* src = (s == 0) ? ohy : (s == 1) ? fhy : (s == 2) ? oeu : feu;
    src += (size_t)b * ND;
    size_t row = (size_t)b * NS + s;
    float* dst = g_gf0 + row * ND;
    __nv_bfloat16* d2 = g_a2 + row * 2 * ND;
    __shared__ float sh[33];
    float f = 1.f;
    if (s < 2) {
        float acc = 0.f;
        for (int i = threadIdx.x; i < ND; i += blockDim.x) { float v = src[i]; acc += v * v; }
        float n2 = blockReduceSum(acc, sh);
        float n = fmaxf(sqrtf(n2), 1e-15f);
        float t = fminf(SQC * n, 1.f - 1e-5f);
        float art = 0.5f * (log1pf(t) - log1pf(-t));
        f = art / (n * SQC);
    }
    for (int i = threadIdx.x; i < ND; i += blockDim.x) {
        float v = src[i] * f;
        dst[i] = v;
        __nv_bfloat16 hi = __float2bfloat16(v);
        __nv_bfloat16 lo = __float2bfloat16(v - __bfloat162float(hi));
        d2[i] = hi; d2[ND + i] = lo;
    }
}

// ---------------- 2) attention (writes context directly as split-bf16 [hi|lo]) ----------------
__global__ void k_attn() {
    int bh = blockIdx.x;
    int b = bh >> 2, h = bh & 3;
    __shared__ float q[NS][HD], kk[NS][HD], v[NS][HD];
    __shared__ float sc[NS][NS];
    int tid = threadIdx.x;
    const float* base = g_qkv + (size_t)b * NS * 3 * ND;
#pragma unroll
    for (int si = 0; si < NS; si++) {
        q [si][tid] = base[si * 3 * ND +          h * HD + tid];
        kk[si][tid] = base[si * 3 * ND + ND     + h * HD + tid];
        v [si][tid] = base[si * 3 * ND + 2 * ND + h * HD + tid];
    }
    __syncthreads();
    int w = tid >> 5, lane = tid & 31;
    for (int p = w; p < 16; p += 8) {
        int i = p >> 2, j = p & 3;
        float s = 0.f;
        for (int d = lane; d < HD; d += 32) s += q[i][d] * kk[j][d];
#pragma unroll
        for (int o = 16; o > 0; o >>= 1) s += __shfl_down_sync(0xffffffffu, s, o);
        if (lane == 0) sc[i][j] = s * 0.0625f;
    }
    __syncthreads();
    if (tid < 4) {
        float s0 = sc[tid][0], s1 = sc[tid][1], s2 = sc[tid][2], s3 = sc[tid][3];
        float m = fmaxf(fmaxf(s0, s1), fmaxf(s2, s3));
        float e0 = expf(s0 - m), e1 = expf(s1 - m), e2 = expf(s2 - m), e3 = expf(s3 - m);
        float inv = 1.f / (e0 + e1 + e2 + e3);
        sc[tid][0] = e0 * inv; sc[tid][1] = e1 * inv; sc[tid][2] = e2 * inv; sc[tid][3] = e3 * inv;
    }
    __syncthreads();
#pragma unroll
    for (int i = 0; i < NS; i++) {
        float o = sc[i][0] * v[0][tid] + sc[i][1] * v[1][tid] + sc[i][2] * v[2][tid] + sc[i][3] * v[3][tid];
        size_t row = (size_t)b * NS + i;
        int col = h * HD + tid;
        __nv_bfloat16 hi = __float2bfloat16(o);
        __nv_bfloat16 lo = __float2bfloat16(o - __bfloat162float(hi));
        __nv_bfloat16* d2 = g_a2 + row * 2 * ND;
        d2[col] = hi; d2[ND + col] = lo;
    }
}

// ---------------- 3) layernorm + l_expmap0 ----------------
__global__ void k_ln_map(const float* __restrict__ ln_w, const float* __restrict__ ln_b,
                         float* __restrict__ dout) {
    int b = blockIdx.x, s = blockIdx.y;
    size_t off = ((size_t)b * NS + s) * ND;
    __shared__ float sh[33];
    int tid = threadIdx.x;
    float x[4];
    float sum = 0.f;
#pragma unroll
    for (int r = 0; r < 4; r++) {
        int i = tid + r * 256;
        x[r] = g_gf0[off + i] + g_attn[off + i];
        sum += x[r];
    }
    float mu = blockReduceSum(sum, sh) * (1.f / ND);
    float vs = 0.f;
#pragma unroll
    for (int r = 0; r < 4; r++) { float d = x[r] - mu; vs += d * d; }
    float var = blockReduceSum(vs, sh) * (1.f / ND);
    float rstd = rsqrtf(var + 1e-5f);
    float y[4];
#pragma unroll
    for (int r = 0; r < 4; r++) {
        int i = tid + r * 256;
        y[r] = (x[r] - mu) * rstd * ln_w[i] + ln_b[i];
    }
    long long base = (s == 0) ? OH_OFF : (s == 1) ? FH_OFF : (s == 2) ? OEU_OFF : FEU_OFF;
    float* dst = dout + base + (size_t)b * ND;
    if (s < 2) {
        float n2acc = 0.f;
#pragma unroll
        for (int r = 0; r < 4; r++) n2acc += y[r] * y[r];
        float n2 = blockReduceSum(n2acc, sh);
        float rc = SQC * sqrtf(n2);
        float si = fminf(fmaxf(rc, EPSF), ASINH_MAX);
        float f = sinhf(si) / fmaxf(rc, EPSF);
#pragma unroll
        for (int r = 0; r < 4; r++) dst[tid + r * 256] = y[r] * f;
    } else {
#pragma unroll
        for (int r = 0; r < 4; r++) dst[tid + r * 256] = y[r];
    }
}

// ---------------- 4) entailment penalties ----------------
__global__ void k_pen(const float* __restrict__ dout) {
    int b = blockIdx.x, which = blockIdx.y;
    const float* u = (which ? g_uf : g_uo) + (size_t)b * ND;
    const float* y = dout + (which ? OH_OFF : FH_OFF) + (size_t)b * ND;
    __shared__ float sh[33];
    int tid = threadIdx.x;
    float su2 = 0.f, suy = 0.f, sy2 = 0.f;
#pragma unroll
    for (int r = 0; r < 4; r++) {
        int i = tid + r * 256;
        float uu = u[i], yy = y[i];
        su2 += uu * uu; suy += uu * yy; sy2 += yy * yy;
    }
    su2 = blockReduceSum(su2, sh);
    suy = blockReduceSum(suy, sh);
    sy2 = blockReduceSum(sy2, sh);
    if (tid == 0) {
        float ru = sqrtf(su2);
        float rc = SQC * ru;
        float si = fminf(fmaxf(rc, EPSF), ASINH_MAX);
        float f = sinhf(si) / fmaxf(rc, EPSF);
        float xx = f * f * su2;
        float xy = f * suy;
        float yy = sy2;
        float nx = f * ru;
        float xt = sqrtf(1.f / CURV + xx);
        float yt = sqrtf(1.f / CURV + yy);
        float cxy = CURV * (xy - xt * yt);
        float num = yt + cxy * xt;
        float den = sqrtf(fmaxf(cxy * cxy - 1.f, EPSF));
        float acos_in = num / (nx * den + EPSF);
        acos_in = fminf(fmaxf(acos_in, -1.f + EPSF), 1.f - EPSF);
        float angle = acosf(acos_in);
        float asin_in = 0.2f / (nx * SQC + EPSF);
        asin_in = fminf(fmaxf(asin_in, -1.f + EPSF), 1.f - EPSF);
        float ap = asinf(asin_in);
        g_pen[which * NB + b] = fmaxf(angle - ap, 0.f);
    }
}

// ---------------- 5) loss reduction ----------------
__global__ void k_loss(const int* __restrict__ mask, float* __restrict__ dout) {
    __shared__ float sh[33];
    int tid = threadIdx.x;
    float so = 0.f, sf = 0.f, cnt = 0.f;
    for (int i = tid; i < NB; i += blockDim.x) {
        so += g_pen[i];
        float m = (float)mask[i];
        sf += g_pen[NB + i] * m;
        cnt += m;
    }
    so = blockReduceSum(so, sh);
    sf = blockReduceSum(sf, sh);
    cnt = blockReduceSum(cnt, sh);
    if (tid == 0) {
        float ol = so * (1.f / NB);
        float fl = (cnt > 0.f) ? sf / fmaxf(cnt, 1.f) : 0.f;
        dout[LOSS_OFF] = ol + fl;
    }
}

// ---------------- 6) per-class MLR constants ----------------
__global__ void k_cls(const float* __restrict__ a, const float* __restrict__ p) {
    int c = blockIdx.x;
    const float* pr = p + (size_t)c * ND;
    const float* ar = a + (size_t)c * ND;
    __shared__ float sh[33];
    int tid = threadIdx.x;
    float sp2 = 0.f, sa2 = 0.f, spa = 0.f;
#pragma unroll
    for (int r = 0; r < 4; r++) {
        int i = tid + r * 256;
        float pv = pr[i], av = ar[i];
        sp2 += pv * pv; sa2 += av * av; spa += pv * av;
    }
    sp2 = blockReduceSum(sp2, sh);
    sa2 = blockReduceSum(sa2, sh);
    spa = blockReduceSum(spa, sh);
    float np = sqrtf(sp2);
    float n = fmaxf(np, 1e-15f);
    float f = tanhf(SQC * n) / (SQC * n);
    float x2 = f * f * sp2;
    float conf = 1.f - CURV * x2;
    float anorm = fabsf(conf) * sqrtf(sa2);
    float kkv = (2.f / conf) * anorm / SQC;
    float pa = f * conf * spa;
#pragma unroll
    for (int r = 0; r < 4; r++) {
        int i = tid + r * 256;
        g_pp[(size_t)c * ND + i] = f * pr[i];
        g_ap[(size_t)c * ND + i] = conf * ar[i];
    }
    if (tid == 0) {
        g_cs[c] = x2; g_cs[NC + c] = anorm; g_cs[2 * NC + c] = kkv; g_cs[3 * NC + c] = pa;
    }
}

// ---------------- 7) fused maps + hyperbolic MLR logits ----------------
__global__ void k_logits(float* __restrict__ dout) {
    int b = blockIdx.x;
    const float* oh = dout + OH_OFF + (size_t)b * ND;
    __shared__ float sy[ND];
    __shared__ float sh[33];
    int tid = threadIdx.x;
    float acc = 0.f;
#pragma unroll
    for (int r = 0; r < 4; r++) {
        int i = tid + r * 256;
        float v = oh[i];
        sy[i] = v;
        acc += v * v;
    }
    float r2 = blockReduceSum(acc, sh);
    float rn = sqrtf(r2);
    float rc = SQC * rn;
    float g1 = asinhf(rc) / fmaxf(rc, EPSF);
    float nu = fmaxf(g1 * rn, 1e-15f);
    float f2 = tanhf(SQC * nu) / (SQC * nu);
    float nw = f2 * (g1 * rn);
    float maxn = (1.f - 0.004f) / SQC;
    float n3 = fmaxf(nw, 1e-15f);
    float scale = (n3 > maxn) ? (maxn / n3) : 1.f;
    float s = g1 * f2 * scale;
    float y2 = s * s * r2;

    int w = tid >> 5, lane = tid & 31;
    for (int c = w; c < NC; c += 8) {
        const float* pp = g_pp + (size_t)c * ND;
        const float* ap = g_ap + (size_t)c * ND;
        float dp = 0.f, da = 0.f;
        for (int i = lane; i < ND; i += 32) {
            float v = sy[i];
            dp += v * pp[i];
            da += v * ap[i];
        }
#pragma unroll
        for (int o = 16; o > 0; o >>= 1) {
            dp += __shfl_down_sync(0xffffffffu, dp, o);
            da += __shfl_down_sync(0xffffffffu, da, o);
        }
        if (lane == 0) {
            float x2 = g_cs[c], anorm = g_cs[NC + c], kkv = g_cs[2 * NC + c], pa = g_cs[3 * NC + c];
            float xy = -s * dp;
            float ya = s * da;
            float A  = 1.f + 2.f * CURV * xy + CURV * y2;
            float Bc = 1.f - CURV * x2;
            float den0 = 1.f + 2.f * CURV * xy + CURV * CURV * x2 * y2 + 1e-5f;
            float mobdot = (A * (-pa) + Bc * ya) / den0;
            float num2 = 2.f * SQC * mobdot;
            float mob2 = (A * A * x2 + Bc * Bc * y2 + 2.f * A * Bc * xy) / (den0 * den0);
            float den2 = anorm * (1.f - CURV * mob2);
            dout[(size_t)b * NC + c] = kkv * asinhf(num2 / den2);
        }
    }
}

// ---------------- launch ----------------
extern "C" void kernel_launch(void* const* d_in, const int* in_sizes, int n_in,
                              void* d_out, int out_size) {
    const float* order_hyp  = (const float*)d_in[0];
    const float* family_hyp = (const float*)d_in[1];
    const float* order_euc  = (const float*)d_in[2];
    const float* family_euc = (const float*)d_in[3];
    const float* order      = (const float*)d_in[4];
    const float* family     = (const float*)d_in[5];
    const int*   mask       = (const int*)  d_in[6];
    const float* in_proj_w  = (const float*)d_in[7];
    const float* in_proj_b  = (const float*)d_in[8];
    const float* out_proj_w = (const float*)d_in[9];
    const float* out_proj_b = (const float*)d_in[10];
    const float* ln_w       = (const float*)d_in[11];
    const float* ln_b       = (const float*)d_in[12];
    const float* to_w       = (const float*)d_in[13];
    const float* to_b       = (const float*)d_in[14];
    const float* tf_w       = (const float*)d_in[15];
    const float* tf_b       = (const float*)d_in[16];
    const float* mlr_a      = (const float*)d_in[17];
    const float* mlr_p      = (const float*)d_in[18];
    float* out = (float*)d_out;

    float *p_qkv, *p_attn, *p_uo, *p_uf;
    __nv_bfloat16 *p_a2, *p_w2;
    cudaGetSymbolAddress((void**)&p_qkv,  g_qkv);
    cudaGetSymbolAddress((void**)&p_attn, g_attn);
    cudaGetSymbolAddress((void**)&p_uo,   g_uo);
    cudaGetSymbolAddress((void**)&p_uf,   g_uf);
    cudaGetSymbolAddress((void**)&p_a2,   g_a2);
    cudaGetSymbolAddress((void**)&p_w2,   g_w2);

    cudaFuncSetAttribute(k_gemm_mma, cudaFuncAttributeMaxDynamicSharedMemorySize, SMEM_GEMM);

    // weight splits [hi | lo]
    k_cvt2<<<dim3(ND / 256, 3 * ND), 256>>>(in_proj_w,  p_w2 + W_IN2_OFF,  ND);
    k_cvt2<<<dim3(ND / 256, ND),     256>>>(out_proj_w, p_w2 + W_OUT2_OFF, ND);
    k_cvt2<<<dim3(NT / 256, ND),     256>>>(to_w,       p_w2 + W_TO2_OFF,  NT);
    k_cvt2<<<dim3(NT / 256, ND),     256>>>(tf_w,       p_w2 + W_TF2_OFF,  NT);

    // 1) stacked features (fp32 residual + split-bf16 activation)
    k_prep_gf<<<dim3(NB, NS), 256>>>(order_hyp, family_hyp, order_euc, family_euc);

    // 2) QKV (split-GEMM, K=1024)
    k_gemm_mma<<<dim3(3 * ND / 128, NB * NS / 128), 256, SMEM_GEMM>>>(
        p_a2, p_w2 + W_IN2_OFF, in_proj_b, p_qkv, NB * NS, 3 * ND, ND);

    // 3) attention (writes ctx split-bf16 into g_a2 directly)
    k_attn<<<NB * NH, HD>>>();

    // 4) out-proj
    k_gemm_mma<<<dim3(ND / 128, NB * NS / 128), 256, SMEM_GEMM>>>(
        p_a2, p_w2 + W_OUT2_OFF, out_proj_b, p_attn, NB * NS, ND, ND);

    // 5) layernorm + l_expmap0 -> d_out
    k_ln_map<<<dim3(NB, NS), 256>>>(ln_w, ln_b, out);

    // 6) text projections (K=768)
    k_cvt2<<<dim3(NT / 256, NB), 256>>>(order,  p_a2, NT);
    k_cvt2<<<dim3(NT / 256, NB), 256>>>(family, p_a2 + FAM2_OFF, NT);
    k_gemm_mma<<<dim3(ND / 128, NB / 128), 256, SMEM_GEMM>>>(
        p_a2, p_w2 + W_TO2_OFF, to_b, p_uo, NB, ND, NT);
    k_gemm_mma<<<dim3(ND / 128, NB / 128), 256, SMEM_GEMM>>>(
        p_a2 + FAM2_OFF, p_w2 + W_TF2_OFF, tf_b, p_uf, NB, ND, NT);

    // 7) penalties + loss
    k_pen<<<dim3(NB, 2), 256>>>(out);
    k_loss<<<1, 1024>>>(mask, out);

    // 8) MLR constants + logits
    k_cls<<<NC, 256>>>(mlr_a, mlr_p);
    k_logits<<<NB, 256>>>(out);
}

// round 17
// speedup vs baseline: 1.5063x; 1.3491x over previous
#include <cuda_runtime.h>
#include <cuda_fp16.h>
#include <math.h>
#include <stdint.h>

// ---------------- problem constants ----------------
constexpr int NB = 4096;   // batch
constexpr int ND = 1024;   // model dim
constexpr int NT = 768;    // text dim
constexpr int NC = 16;     // classes
constexpr int NH = 4;      // heads
constexpr int NS = 4;      // sequence length of stacked features
constexpr int HD = ND / NH; // 256

#define CURV 0.05f
#define SQC  0.22360679774997896f       // sqrt(0.05)
#define EPSF 1e-8f
#define ASINH_MAX 11.090354888959125f   // arcsinh(2^15)

// output layout (flattened tuple: logits, loss, oh, fh, oeu, feu)
constexpr long long LOSS_OFF = (long long)NB * NC;
constexpr long long OH_OFF   = LOSS_OFF + 1;
constexpr long long FH_OFF   = OH_OFF  + (long long)NB * ND;
constexpr long long OEU_OFF  = FH_OFF  + (long long)NB * ND;
constexpr long long FEU_OFF  = OEU_OFF + (long long)NB * ND;

// ---------------- device scratch ----------------
__device__ float g_gf0 [(size_t)NB * NS * ND];
__device__ float g_qkv [(size_t)NB * NS * 3 * ND];
__device__ float g_attn[(size_t)NB * NS * ND];
__device__ float g_uo  [(size_t)NB * ND];
__device__ float g_uf  [(size_t)NB * ND];
__device__ float g_pen [2 * NB];
__device__ float g_pp  [NC * ND];
__device__ float g_ap  [NC * ND];
__device__ float g_cs  [4 * NC];

// split-fp16 activations [hi | lo] (row length 2K); reused gf0 -> ctx -> order+family
__device__ __half g_a2[(size_t)NB * NS * 2 * ND];
// weights: single fp16
constexpr size_t W_IN1_OFF  = 0;                                 // 3072 x 1024
constexpr size_t W_OUT1_OFF = W_IN1_OFF  + (size_t)3 * ND * ND;  // 1024 x 1024
constexpr size_t W_TO1_OFF  = W_OUT1_OFF + (size_t)ND * ND;      // 1024 x 768
constexpr size_t W_TF1_OFF  = W_TO1_OFF  + (size_t)ND * NT;
__device__ __half g_w1[W_TF1_OFF + (size_t)ND * NT];
constexpr size_t FAM2_OFF = (size_t)NB * 2 * NT;

// ---------------- small helpers ----------------
__device__ __forceinline__ float blockReduceSum(float v, volatile float* sh) {
    int lane = threadIdx.x & 31, wid = threadIdx.x >> 5;
#pragma unroll
    for (int o = 16; o > 0; o >>= 1) v += __shfl_down_sync(0xffffffffu, v, o);
    if (lane == 0) sh[wid] = v;
    __syncthreads();
    if (wid == 0) {
        int nw = (blockDim.x + 31) >> 5;
        float t = (lane < nw) ? sh[lane] : 0.f;
#pragma unroll
        for (int o = 16; o > 0; o >>= 1) t += __shfl_down_sync(0xffffffffu, t, o);
        if (lane == 0) sh[32] = t;
    }
    __syncthreads();
    float r = sh[32];
    __syncthreads();
    return r;
}

__device__ __forceinline__ uint32_t smem_u32(const void* p) {
    uint32_t a;
    asm("{ .reg .u64 t; cvta.to.shared.u64 t, %1; cvt.u32.u64 %0, t; }" : "=r"(a) : "l"(p));
    return a;
}

// SW64 swizzle for 64-byte rows: bits [5:4] ^= bits [8:7]
#define SWZ64(o) ((o) ^ (((o) >> 3) & 0x30))

__device__ __forceinline__ void cp16(uint32_t dst, const void* src) {
    asm volatile("cp.async.cg.shared.global [%0], [%1], 16;" :: "r"(dst), "l"(src));
}
__device__ __forceinline__ void cp_commit() {
    asm volatile("cp.async.commit_group;" ::: "memory");
}
__device__ __forceinline__ void cp_wait1() {
    asm volatile("cp.async.wait_group 1;" ::: "memory");
}
__device__ __forceinline__ void ldm4(uint32_t* r, uint32_t a) {
    asm volatile("ldmatrix.sync.aligned.m8n8.x4.shared.b16 {%0,%1,%2,%3}, [%4];"
                 : "=r"(r[0]), "=r"(r[1]), "=r"(r[2]), "=r"(r[3]) : "r"(a));
}
__device__ __forceinline__ void mma16816(float* d, const uint32_t* a, uint32_t b0, uint32_t b1) {
    asm volatile(
        "mma.sync.aligned.m16n8k16.row.col.f32.f16.f16.f32 "
        "{%0,%1,%2,%3},{%4,%5,%6,%7},{%8,%9},{%0,%1,%2,%3};"
        : "+f"(d[0]), "+f"(d[1]), "+f"(d[2]), "+f"(d[3])
        : "r"(a[0]), "r"(a[1]), "r"(a[2]), "r"(a[3]), "r"(b0), "r"(b1));
}

// ---------------- split-GEMM: C = (Ah + Al) @ B^T + bias ----------------
// A2 = [ah|al] fp16 (row length 2K), B = fp16 weights (row length K).
// Per 32-wide K chunk: load 3 tiles (Ah, Al, B; 128x32 fp16 = 8KB, 64B rows SW64),
// run 2 MMA bursts reusing B fragments.
constexpr uint32_t TILE3   = 128 * 64;          // 8 KB
constexpr uint32_t STAGE3  = 3 * TILE3;         // 24 KB
constexpr int      STAGES  = 3;
constexpr uint32_t SMEM_GEMM = STAGES * STAGE3; // 72 KB

__device__ __forceinline__ void load_stage3(uint32_t sb, int s,
                                            const __half* Ab, const __half* Bb,
                                            int K, int kc, int tid) {
    uint32_t st = sb + (uint32_t)s * STAGE3;
    int K2 = 2 * K;
#pragma unroll
    for (int u = 0; u < 6; u++) {
        int id = tid + u * 256;          // 0..1535
        int tile = id >> 9;              // 0:Ah 1:Al 2:B
        int w = id & 511;
        int row = w >> 2, ch = w & 3;
        uint32_t so = st + (uint32_t)tile * TILE3 + SWZ64((uint32_t)row * 64 + ch * 16);
        const void* src;
        if (tile == 2) src = Bb + (size_t)row * K + kc * 32 + ch * 8;
        else           src = Ab + (size_t)row * K2 + kc * 32 + ch * 8 + (tile ? K : 0);
        cp16(so, src);
    }
    cp_commit();
}

__global__ __launch_bounds__(256, 2)
void k_gemm_mma(const __half* __restrict__ A, const __half* __restrict__ B,
                const float* __restrict__ bias, float* __restrict__ C,
                int M, int N, int K) {
    extern __shared__ char smem[];
    uint32_t sb = smem_u32(smem);
    int tid = threadIdx.x, wid = tid >> 5, lane = tid & 31;
    int wm = wid >> 1, wn = wid & 1;           // 4x2 warp grid
    int lr = lane & 7, mi = lane >> 3;

    int bm = blockIdx.y * 128;
    int bn = blockIdx.x * 128;
    const __half* Ab = A + (size_t)bm * 2 * K;
    const __half* Bb = B + (size_t)bn * K;
    const int NK = K >> 5;                      // 32 real-k per chunk

    // ldmatrix per-lane addresses (64B rows)
    int aR = wm * 32 + lr + (mi & 1) * 8;
    uint32_t aKh = (uint32_t)(mi >> 1) * 16;
    uint32_t xa = (uint32_t)((aR >> 1) & 3) * 16;
    uint32_t aOff0 = (uint32_t)aR * 64;
    uint32_t aOff1 = aOff0 + 16 * 64;
    int bR = wn * 64 + lr + (mi >> 1) * 8;
    uint32_t bKh = (uint32_t)(mi & 1) * 16;
    uint32_t xb = (uint32_t)((bR >> 1) & 3) * 16;
    uint32_t bOff[4];
#pragma unroll
    for (int j2 = 0; j2 < 4; j2++) bOff[j2] = (uint32_t)(bR + j2 * 16) * 64;

    float acc[2][8][4];
#pragma unroll
    for (int i = 0; i < 2; i++)
#pragma unroll
        for (int j = 0; j < 8; j++)
#pragma unroll
            for (int r = 0; r < 4; r++) acc[i][j][r] = 0.f;

    load_stage3(sb, 0, Ab, Bb, K, 0, tid);
    load_stage3(sb, 1, Ab, Bb, K, 1, tid);

    for (int kt = 0; kt < NK; kt++) {
        cp_wait1();
        __syncthreads();
        if (kt + 2 < NK) load_stage3(sb, (kt + 2) % STAGES, Ab, Bb, K, kt + 2, tid);
        else cp_commit();

        uint32_t st = sb + (uint32_t)(kt % STAGES) * STAGE3;
        uint32_t aH = st, aL = st + TILE3, bT = st + 2 * TILE3;
#pragma unroll
        for (int ks = 0; ks < 2; ks++) {
            uint32_t kb = (uint32_t)ks * 32;
            uint32_t aSel = (kb + aKh) ^ xa;
            uint32_t bSel = (kb + bKh) ^ xb;
            uint32_t ahf[2][4], alf[2][4], bf[4][4];
            // burst 1: Ah * B
            ldm4(ahf[0], aH + aOff0 + aSel);
            ldm4(ahf[1], aH + aOff1 + aSel);
#pragma unroll
            for (int j2 = 0; j2 < 4; j2++) ldm4(bf[j2], bT + bOff[j2] + bSel);
#pragma unroll
            for (int i = 0; i < 2; i++)
#pragma unroll
                for (int j = 0; j < 8; j++)
                    mma16816(acc[i][j], ahf[i], bf[j >> 1][(j & 1) * 2], bf[j >> 1][(j & 1) * 2 + 1]);
            // burst 2: Al * B (reuse B fragments)
            ldm4(alf[0], aL + aOff0 + aSel);
            ldm4(alf[1], aL + aOff1 + aSel);
#pragma unroll
            for (int i = 0; i < 2; i++)
#pragma unroll
                for (int j = 0; j < 8; j++)
                    mma16816(acc[i][j], alf[i], bf[j >> 1][(j & 1) * 2], bf[j >> 1][(j & 1) * 2 + 1]);
        }
    }

    // epilogue: direct float2 stores with bias
    int mBase = bm + wm * 32 + (lane >> 2);
    int nBase = bn + wn * 64 + 2 * (lane & 3);
#pragma unroll
    for (int i = 0; i < 2; i++) {
        int m0 = mBase + i * 16;
#pragma unroll
        for (int j = 0; j < 8; j++) {
            int n = nBase + j * 8;
            float bx = bias[n], by = bias[n + 1];
            float2 v0 = { acc[i][j][0] + bx, acc[i][j][1] + by };
            float2 v1 = { acc[i][j][2] + bx, acc[i][j][3] + by };
            *(float2*)(C + (size_t)m0 * N + n) = v0;
            *(float2*)(C + (size_t)(m0 + 8) * N + n) = v1;
        }
    }
}

// ---------------- converters ----------------
// activations: [hi | lo] fp16 split
__global__ void k_cvt2(const float* __restrict__ src, __half* __restrict__ dst, int K) {
    int r = blockIdx.y;
    int k = blockIdx.x * 256 + threadIdx.x;
    float x = src[(size_t)r * K + k];
    __half hi = __float2half(x);
    __half lo = __float2half(x - __half2float(hi));
    size_t b2 = (size_t)r * 2 * K;
    dst[b2 + k] = hi;
    dst[b2 + K + k] = lo;
}
// weights: single fp16
__global__ void k_cvtw(const float* __restrict__ src, __half* __restrict__ dst) {
    size_t i = (size_t)blockIdx.x * 256 + threadIdx.x;
    dst[i] = __float2half(src[i]);
}

// ---------------- 1) gf0 = stack(p_logmap0(oh), p_logmap0(fh), oeu, feu) + split ----------------
__global__ void k_prep_gf(const float* __restrict__ ohy, const float* __restrict__ fhy,
                          const float* __restrict__ oeu, const float* __restrict__ feu) {
    int b = blockIdx.x, s = blockIdx.y;
    const float* src = (s == 0) ? ohy : (s == 1) ? fhy : (s == 2) ? oeu : feu;
    src += (size_t)b * ND;
    size_t row = (size_t)b * NS + s;
    float* dst = g_gf0 + row * ND;
    __half* d2 = g_a2 + row * 2 * ND;
    __shared__ float sh[33];
    float f = 1.f;
    if (s < 2) {
        float acc = 0.f;
        for (int i = threadIdx.x; i < ND; i += blockDim.x) { float v = src[i]; acc += v * v; }
        float n2 = blockReduceSum(acc, sh);
        float n = fmaxf(sqrtf(n2), 1e-15f);
        float t = fminf(SQC * n, 1.f - 1e-5f);
        float art = 0.5f * (log1pf(t) - log1pf(-t));
        f = art / (n * SQC);
    }
    for (int i = threadIdx.x; i < ND; i += blockDim.x) {
        float v = src[i] * f;
        dst[i] = v;
        __half hi = __float2half(v);
        __half lo = __float2half(v - __half2float(hi));
        d2[i] = hi; d2[ND + i] = lo;
    }
}

// ---------------- 2) attention (writes context directly as split-fp16 [hi|lo]) ----------------
__global__ void k_attn() {
    int bh = blockIdx.x;
    int b = bh >> 2, h = bh & 3;
    __shared__ float q[NS][HD], kk[NS][HD], v[NS][HD];
    __shared__ float sc[NS][NS];
    int tid = threadIdx.x;
    const float* base = g_qkv + (size_t)b * NS * 3 * ND;
#pragma unroll
    for (int si = 0; si < NS; si++) {
        q [si][tid] = base[si * 3 * ND +          h * HD + tid];
        kk[si][tid] = base[si * 3 * ND + ND     + h * HD + tid];
        v [si][tid] = base[si * 3 * ND + 2 * ND + h * HD + tid];
    }
    __syncthreads();
    int w = tid >> 5, lane = tid & 31;
    for (int p = w; p < 16; p += 8) {
        int i = p >> 2, j = p & 3;
        float s = 0.f;
        for (int d = lane; d < HD; d += 32) s += q[i][d] * kk[j][d];
#pragma unroll
        for (int o = 16; o > 0; o >>= 1) s += __shfl_down_sync(0xffffffffu, s, o);
        if (lane == 0) sc[i][j] = s * 0.0625f;
    }
    __syncthreads();
    if (tid < 4) {
        float s0 = sc[tid][0], s1 = sc[tid][1], s2 = sc[tid][2], s3 = sc[tid][3];
        float m = fmaxf(fmaxf(s0, s1), fmaxf(s2, s3));
        float e0 = expf(s0 - m), e1 = expf(s1 - m), e2 = expf(s2 - m), e3 = expf(s3 - m);
        float inv = 1.f / (e0 + e1 + e2 + e3);
        sc[tid][0] = e0 * inv; sc[tid][1] = e1 * inv; sc[tid][2] = e2 * inv; sc[tid][3] = e3 * inv;
    }
    __syncthreads();
#pragma unroll
    for (int i = 0; i < NS; i++) {
        float o = sc[i][0] * v[0][tid] + sc[i][1] * v[1][tid] + sc[i][2] * v[2][tid] + sc[i][3] * v[3][tid];
        size_t row = (size_t)b * NS + i;
        int col = h * HD + tid;
        __half hi = __float2half(o);
        __half lo = __float2half(o - __half2float(hi));
        __half* d2 = g_a2 + row * 2 * ND;
        d2[col] = hi; d2[ND + col] = lo;
    }
}

// ---------------- 3) layernorm + l_expmap0 ----------------
__global__ void k_ln_map(const float* __restrict__ ln_w, const float* __restrict__ ln_b,
                         float* __restrict__ dout) {
    int b = blockIdx.x, s = blockIdx.y;
    size_t off = ((size_t)b * NS + s) * ND;
    __shared__ float sh[33];
    int tid = threadIdx.x;
    float x[4];
    float sum = 0.f;
#pragma unroll
    for (int r = 0; r < 4; r++) {
        int i = tid + r * 256;
        x[r] = g_gf0[off + i] + g_attn[off + i];
        sum += x[r];
    }
    float mu = blockReduceSum(sum, sh) * (1.f / ND);
    float vs = 0.f;
#pragma unroll
    for (int r = 0; r < 4; r++) { float d = x[r] - mu; vs += d * d; }
    float var = blockReduceSum(vs, sh) * (1.f / ND);
    float rstd = rsqrtf(var + 1e-5f);
    float y[4];
#pragma unroll
    for (int r = 0; r < 4; r++) {
        int i = tid + r * 256;
        y[r] = (x[r] - mu) * rstd * ln_w[i] + ln_b[i];
    }
    long long base = (s == 0) ? OH_OFF : (s == 1) ? FH_OFF : (s == 2) ? OEU_OFF : FEU_OFF;
    float* dst = dout + base + (size_t)b * ND;
    if (s < 2) {
        float n2acc = 0.f;
#pragma unroll
        for (int r = 0; r < 4; r++) n2acc += y[r] * y[r];
        float n2 = blockReduceSum(n2acc, sh);
        float rc = SQC * sqrtf(n2);
        float si = fminf(fmaxf(rc, EPSF), ASINH_MAX);
        float f = sinhf(si) / fmaxf(rc, EPSF);
#pragma unroll
        for (int r = 0; r < 4; r++) dst[tid + r * 256] = y[r] * f;
    } else {
#pragma unroll
        for (int r = 0; r < 4; r++) dst[tid + r * 256] = y[r];
    }
}

// ---------------- 4) entailment penalties ----------------
__global__ void k_pen(const float* __restrict__ dout) {
    int b = blockIdx.x, which = blockIdx.y;
    const float* u = (which ? g_uf : g_uo) + (size_t)b * ND;
    const float* y = dout + (which ? OH_OFF : FH_OFF) + (size_t)b * ND;
    __shared__ float sh[33];
    int tid = threadIdx.x;
    float su2 = 0.f, suy = 0.f, sy2 = 0.f;
#pragma unroll
    for (int r = 0; r < 4; r++) {
        int i = tid + r * 256;
        float uu = u[i], yy = y[i];
        su2 += uu * uu; suy += uu * yy; sy2 += yy * yy;
    }
    su2 = blockReduceSum(su2, sh);
    suy = blockReduceSum(suy, sh);
    sy2 = blockReduceSum(sy2, sh);
    if (tid == 0) {
        float ru = sqrtf(su2);
        float rc = SQC * ru;
        float si = fminf(fmaxf(rc, EPSF), ASINH_MAX);
        float f = sinhf(si) / fmaxf(rc, EPSF);
        float xx = f * f * su2;
        float xy = f * suy;
        float yy = sy2;
        float nx = f * ru;
        float xt = sqrtf(1.f / CURV + xx);
        float yt = sqrtf(1.f / CURV + yy);
        float cxy = CURV * (xy - xt * yt);
        float num = yt + cxy * xt;
        float den = sqrtf(fmaxf(cxy * cxy - 1.f, EPSF));
        float acos_in = num / (nx * den + EPSF);
        acos_in = fminf(fmaxf(acos_in, -1.f + EPSF), 1.f - EPSF);
        float angle = acosf(acos_in);
        float asin_in = 0.2f / (nx * SQC + EPSF);
        asin_in = fminf(fmaxf(asin_in, -1.f + EPSF), 1.f - EPSF);
        float ap = asinf(asin_in);
        g_pen[which * NB + b] = fmaxf(angle - ap, 0.f);
    }
}

// ---------------- 5) loss reduction ----------------
__global__ void k_loss(const int* __restrict__ mask, float* __restrict__ dout) {
    __shared__ float sh[33];
    int tid = threadIdx.x;
    float so = 0.f, sf = 0.f, cnt = 0.f;
    for (int i = tid; i < NB; i += blockDim.x) {
        so += g_pen[i];
        float m = (float)mask[i];
        sf += g_pen[NB + i] * m;
        cnt += m;
    }
    so = blockReduceSum(so, sh);
    sf = blockReduceSum(sf, sh);
    cnt = blockReduceSum(cnt, sh);
    if (tid == 0) {
        float ol = so * (1.f / NB);
        float fl = (cnt > 0.f) ? sf / fmaxf(cnt, 1.f) : 0.f;
        dout[LOSS_OFF] = ol + fl;
    }
}

// ---------------- 6) per-class MLR constants ----------------
__global__ void k_cls(const float* __restrict__ a, const float* __restrict__ p) {
    int c = blockIdx.x;
    const float* pr = p + (size_t)c * ND;
    const float* ar = a + (size_t)c * ND;
    __shared__ float sh[33];
    int tid = threadIdx.x;
    float sp2 = 0.f, sa2 = 0.f, spa = 0.f;
#pragma unroll
    for (int r = 0; r < 4; r++) {
        int i = tid + r * 256;
        float pv = pr[i], av = ar[i];
        sp2 += pv * pv; sa2 += av * av; spa += pv * av;
    }
    sp2 = blockReduceSum(sp2, sh);
    sa2 = blockReduceSum(sa2, sh);
    spa = blockReduceSum(spa, sh);
    float np = sqrtf(sp2);
    float n = fmaxf(np, 1e-15f);
    float f = tanhf(SQC * n) / (SQC * n);
    float x2 = f * f * sp2;
    float conf = 1.f - CURV * x2;
    float anorm = fabsf(conf) * sqrtf(sa2);
    float kkv = (2.f / conf) * anorm / SQC;
    float pa = f * conf * spa;
#pragma unroll
    for (int r = 0; r < 4; r++) {
        int i = tid + r * 256;
        g_pp[(size_t)c * ND + i] = f * pr[i];
        g_ap[(size_t)c * ND + i] = conf * ar[i];
    }
    if (tid == 0) {
        g_cs[c] = x2; g_cs[NC + c] = anorm; g_cs[2 * NC + c] = kkv; g_cs[3 * NC + c] = pa;
    }
}

// ---------------- 7) fused maps + hyperbolic MLR logits ----------------
__global__ void k_logits(float* __restrict__ dout) {
    int b = blockIdx.x;
    const float* oh = dout + OH_OFF + (size_t)b * ND;
    __shared__ float sy[ND];
    __shared__ float sh[33];
    int tid = threadIdx.x;
    float acc = 0.f;
#pragma unroll
    for (int r = 0; r < 4; r++) {
        int i = tid + r * 256;
        float v = oh[i];
        sy[i] = v;
        acc += v * v;
    }
    float r2 = blockReduceSum(acc, sh);
    float rn = sqrtf(r2);
    float rc = SQC * rn;
    float g1 = asinhf(rc) / fmaxf(rc, EPSF);
    float nu = fmaxf(g1 * rn, 1e-15f);
    float f2 = tanhf(SQC * nu) / (SQC * nu);
    float nw = f2 * (g1 * rn);
    float maxn = (1.f - 0.004f) / SQC;
    float n3 = fmaxf(nw, 1e-15f);
    float scale = (n3 > maxn) ? (maxn / n3) : 1.f;
    float s = g1 * f2 * scale;
    float y2 = s * s * r2;

    int w = tid >> 5, lane = tid & 31;
    for (int c = w; c < NC; c += 8) {
        const float* pp = g_pp + (size_t)c * ND;
        const float* ap = g_ap + (size_t)c * ND;
        float dp = 0.f, da = 0.f;
        for (int i = lane; i < ND; i += 32) {
            float v = sy[i];
            dp += v * pp[i];
            da += v * ap[i];
        }
#pragma unroll
        for (int o = 16; o > 0; o >>= 1) {
            dp += __shfl_down_sync(0xffffffffu, dp, o);
            da += __shfl_down_sync(0xffffffffu, da, o);
        }
        if (lane == 0) {
            float x2 = g_cs[c], anorm = g_cs[NC + c], kkv = g_cs[2 * NC + c], pa = g_cs[3 * NC + c];
            float xy = -s * dp;
            float ya = s * da;
            float A  = 1.f + 2.f * CURV * xy + CURV * y2;
            float Bc = 1.f - CURV * x2;
            float den0 = 1.f + 2.f * CURV * xy + CURV * CURV * x2 * y2 + 1e-5f;
            float mobdot = (A * (-pa) + Bc * ya) / den0;
            float num2 = 2.f * SQC * mobdot;
            float mob2 = (A * A * x2 + Bc * Bc * y2 + 2.f * A * Bc * xy) / (den0 * den0);
            float den2 = anorm * (1.f - CURV * mob2);
            dout[(size_t)b * NC + c] = kkv * asinhf(num2 / den2);
        }
    }
}

// ---------------- launch ----------------
extern "C" void kernel_launch(void* const* d_in, const int* in_sizes, int n_in,
                              void* d_out, int out_size) {
    const float* order_hyp  = (const float*)d_in[0];
    const float* family_hyp = (const float*)d_in[1];
    const float* order_euc  = (const float*)d_in[2];
    const float* family_euc = (const float*)d_in[3];
    const float* order      = (const float*)d_in[4];
    const float* family     = (const float*)d_in[5];
    const int*   mask       = (const int*)  d_in[6];
    const float* in_proj_w  = (const float*)d_in[7];
    const float* in_proj_b  = (const float*)d_in[8];
    const float* out_proj_w = (const float*)d_in[9];
    const float* out_proj_b = (const float*)d_in[10];
    const float* ln_w       = (const float*)d_in[11];
    const float* ln_b       = (const float*)d_in[12];
    const float* to_w       = (const float*)d_in[13];
    const float* to_b       = (const float*)d_in[14];
    const float* tf_w       = (const float*)d_in[15];
    const float* tf_b       = (const float*)d_in[16];
    const float* mlr_a      = (const float*)d_in[17];
    const float* mlr_p      = (const float*)d_in[18];
    float* out = (float*)d_out;

    float *p_qkv, *p_attn, *p_uo, *p_uf;
    __half *p_a2, *p_w1;
    cudaGetSymbolAddress((void**)&p_qkv,  g_qkv);
    cudaGetSymbolAddress((void**)&p_attn, g_attn);
    cudaGetSymbolAddress((void**)&p_uo,   g_uo);
    cudaGetSymbolAddress((void**)&p_uf,   g_uf);
    cudaGetSymbolAddress((void**)&p_a2,   g_a2);
    cudaGetSymbolAddress((void**)&p_w1,   g_w1);

    cudaFuncSetAttribute(k_gemm_mma, cudaFuncAttributeMaxDynamicSharedMemorySize, SMEM_GEMM);

    // weight conversions (single fp16)
    k_cvtw<<<(3 * ND * ND) / 256, 256>>>(in_proj_w,  p_w1 + W_IN1_OFF);
    k_cvtw<<<(ND * ND) / 256,     256>>>(out_proj_w, p_w1 + W_OUT1_OFF);
    k_cvtw<<<(ND * NT) / 256,     256>>>(to_w,       p_w1 + W_TO1_OFF);
    k_cvtw<<<(ND * NT) / 256,     256>>>(tf_w,       p_w1 + W_TF1_OFF);

    // 1) stacked features (fp32 residual + split-fp16 activation)
    k_prep_gf<<<dim3(NB, NS), 256>>>(order_hyp, family_hyp, order_euc, family_euc);

    // 2) QKV (split-GEMM, K=1024)
    k_gemm_mma<<<dim3(3 * ND / 128, NB * NS / 128), 256, SMEM_GEMM>>>(
        p_a2, p_w1 + W_IN1_OFF, in_proj_b, p_qkv, NB * NS, 3 * ND, ND);

    // 3) attention (writes ctx split-fp16 into g_a2 directly)
    k_attn<<<NB * NH, HD>>>();

    // 4) out-proj
    k_gemm_mma<<<dim3(ND / 128, NB * NS / 128), 256, SMEM_GEMM>>>(
        p_a2, p_w1 + W_OUT1_OFF, out_proj_b, p_attn, NB * NS, ND, ND);

    // 5) layernorm + l_expmap0 -> d_out
    k_ln_map<<<dim3(NB, NS), 256>>>(ln_w, ln_b, out);

    // 6) text projections (K=768)
    k_cvt2<<<dim3(NT / 256, NB), 256>>>(order,  p_a2, NT);
    k_cvt2<<<dim3(NT / 256, NB), 256>>>(family, p_a2 + FAM2_OFF, NT);
    k_gemm_mma<<<dim3(ND / 128, NB / 128), 256, SMEM_GEMM>>>(
        p_a2, p_w1 + W_TO1_OFF, to_b, p_uo, NB, ND, NT);
    k_gemm_mma<<<dim3(ND / 128, NB / 128), 256, SMEM_GEMM>>>(
        p_a2 + FAM2_OFF, p_w1 + W_TF1_OFF, tf_b, p_uf, NB, ND, NT);

    // 7) penalties + loss
    k_pen<<<dim3(NB, 2), 256>>>(out);
    k_loss<<<1, 1024>>>(mask, out);

    // 8) MLR constants + logits
    k_cls<<<NC, 256>>>(mlr_a, mlr_p);
    k_logits<<<NB, 256>>>(out);
}